// round 10
// baseline (speedup 1.0000x reference)
#include <cuda_runtime.h>
#include <cuda_bf16.h>
#include <cstdint>

// ---------------------------------------------------------------------------
// TensorNet interaction.
//   msg[n] = (component tensors of n) * (per-node scalar sums of edge MLP),
//   so the graph part is a scatter-add of 96 edge-MLP outputs into acc[n][96].
//
// R10: edge kernel __launch_bounds__(256,2) to force regs<=128 and guarantee
//      2 CTAs/SM (hypothesis: it was reg-limited to 1 CTA = 12.5% occ,
//      explaining 43% issue efficiency). B-fragment hi/lo pairs interleaved
//      into one uint4 -> LDS.128, halving B-frag LDS issues in both kernels.
// ---------------------------------------------------------------------------

#define MAXN 50000
#define PI_F 3.14159265358979323846f
#define CUTOFF_F 5.0f

__device__ float g_acc[(size_t)MAXN * 96];

__device__ __forceinline__ float silu_f(float v) {
    return v * __fdividef(1.0f, 1.0f + __expf(-v));
}
__device__ __forceinline__ uint32_t packbf(float lo, float hi) {
    uint32_t r;
    asm("cvt.rn.bf16x2.f32 %0, %1, %2;" : "=r"(r) : "f"(hi), "f"(lo));
    return r;
}
__device__ __forceinline__ float bf16val(float v) {
    return __bfloat162float(__float2bfloat16(v));
}
__device__ __forceinline__ void pack_hl(float x, float y, uint32_t& h, uint32_t& l) {
    h = packbf(x, y);
    l = packbf(x - bf16val(x), y - bf16val(y));
}
__device__ __forceinline__ void mma_bf16(float c[4], const uint32_t a[4], uint32_t bx, uint32_t by) {
    asm volatile(
        "mma.sync.aligned.m16n8k16.row.col.f32.bf16.bf16.f32 "
        "{%0,%1,%2,%3}, {%4,%5,%6,%7}, {%8,%9}, {%0,%1,%2,%3};"
        : "+f"(c[0]), "+f"(c[1]), "+f"(c[2]), "+f"(c[3])
        : "r"(a[0]), "r"(a[1]), "r"(a[2]), "r"(a[3]), "r"(bx), "r"(by));
}
// one LDS.128 fragment: {h0,h1,l0,l1}; issue 3-term split
__device__ __forceinline__ void mma3(float c[4], const uint32_t ah[4],
                                     const uint32_t al[4], uint4 B) {
    mma_bf16(c, ah, B.x, B.y);
    mma_bf16(c, al, B.x, B.y);
    mma_bf16(c, ah, B.z, B.w);
}

// ---------------------------------------------------------------------------
// Edge MLP kernel. Warp = 16-edge strip.
__global__ void __launch_bounds__(256, 2)
edge_mma_kernel(const float* __restrict__ edge_attr,
                const int*   __restrict__ edge_index,
                const float* __restrict__ edge_weight,
                const float* __restrict__ W1, const float* __restrict__ b1,
                const float* __restrict__ W2, const float* __restrict__ b2,
                const float* __restrict__ W3, const float* __restrict__ b3,
                int E)
{
    __shared__ uint4 sB1[8][32];    // {h0,h1,l0,l1}
    __shared__ uint4 sB2[16][32];
    __shared__ uint4 sB3[48][32];
    __shared__ float sb1[32], sb2[64], sb3[96];

    const int tid = threadIdx.x;

    {
        int i = tid;
        int f = i >> 5, l = i & 31;
        int nt = f >> 1, kf = f & 1;
        int n = nt * 8 + (l >> 2), k0 = kf * 16 + ((l & 3) << 1);
        const float* Wr = W1 + n * 32 + k0;
        uint32_t h0, l0, h1, l1;
        pack_hl(Wr[0], Wr[1], h0, l0);
        pack_hl(Wr[8], Wr[9], h1, l1);
        sB1[f][l] = make_uint4(h0, h1, l0, l1);
    }
    for (int i = tid; i < 512; i += 256) {
        int f = i >> 5, l = i & 31;
        int nt = f >> 1, kf = f & 1;
        int n = nt * 8 + (l >> 2), k0 = kf * 16 + ((l & 3) << 1);
        const float* Wr = W2 + n * 32 + k0;
        uint32_t h0, l0, h1, l1;
        pack_hl(Wr[0], Wr[1], h0, l0);
        pack_hl(Wr[8], Wr[9], h1, l1);
        sB2[f][l] = make_uint4(h0, h1, l0, l1);
    }
    for (int i = tid; i < 1536; i += 256) {
        int f = i >> 5, l = i & 31;
        int nt = f >> 2, kf = f & 3;
        int n = nt * 8 + (l >> 2), k0 = kf * 16 + ((l & 3) << 1);
        const float* Wr = W3 + n * 64 + k0;
        uint32_t h0, l0, h1, l1;
        pack_hl(Wr[0], Wr[1], h0, l0);
        pack_hl(Wr[8], Wr[9], h1, l1);
        sB3[f][l] = make_uint4(h0, h1, l0, l1);
    }
    if (tid < 32) sb1[tid] = b1[tid];
    if (tid < 64) sb2[tid] = b2[tid];
    if (tid < 96) sb3[tid] = b3[tid];
    __syncthreads();

    const int wid = tid >> 5, lane = tid & 31;
    const int r1 = lane >> 2;
    const int tig = lane & 3;
    const int q  = tig << 1;
    const int nStrips = (E + 15) >> 4;

    for (int strip = blockIdx.x * 8 + wid; strip < nStrips;
         strip += gridDim.x * 8) {
        int e0 = strip << 4;
        int eA = e0 + r1, eB = eA + 8;
        int eAc = min(eA, E - 1), eBc = min(eB, E - 1);

        uint32_t A1h[2][4], A1l[2][4];
        #pragma unroll
        for (int kf = 0; kf < 2; kf++) {
            const float* pa = edge_attr + (size_t)eAc * 32 + kf * 16 + q;
            const float* pb = edge_attr + (size_t)eBc * 32 + kf * 16 + q;
            float2 v0 = *(const float2*)pa;
            float2 v1 = *(const float2*)pb;
            float2 v2 = *(const float2*)(pa + 8);
            float2 v3 = *(const float2*)(pb + 8);
            pack_hl(v0.x, v0.y, A1h[kf][0], A1l[kf][0]);
            pack_hl(v1.x, v1.y, A1h[kf][1], A1l[kf][1]);
            pack_hl(v2.x, v2.y, A1h[kf][2], A1l[kf][2]);
            pack_hl(v3.x, v3.y, A1h[kf][3], A1l[kf][3]);
        }

        float D1[4][4];
        #pragma unroll
        for (int nt = 0; nt < 4; nt++) {
            float bb0 = sb1[nt * 8 + q], bb1 = sb1[nt * 8 + q + 1];
            D1[nt][0] = bb0; D1[nt][1] = bb1; D1[nt][2] = bb0; D1[nt][3] = bb1;
            #pragma unroll
            for (int kf = 0; kf < 2; kf++)
                mma3(D1[nt], A1h[kf], A1l[kf], sB1[nt * 2 + kf][lane]);
        }

        uint32_t A2h[2][4], A2l[2][4];
        #pragma unroll
        for (int kf = 0; kf < 2; kf++) {
            int na = 2 * kf, nb = 2 * kf + 1;
            float sa0 = silu_f(D1[na][0]), sa1 = silu_f(D1[na][1]);
            float sa2 = silu_f(D1[na][2]), sa3 = silu_f(D1[na][3]);
            float sb0 = silu_f(D1[nb][0]), sb1v = silu_f(D1[nb][1]);
            float sb2v = silu_f(D1[nb][2]), sb3v = silu_f(D1[nb][3]);
            pack_hl(sa0, sa1, A2h[kf][0], A2l[kf][0]);
            pack_hl(sa2, sa3, A2h[kf][1], A2l[kf][1]);
            pack_hl(sb0, sb1v, A2h[kf][2], A2l[kf][2]);
            pack_hl(sb2v, sb3v, A2h[kf][3], A2l[kf][3]);
        }

        float D2[8][4];
        #pragma unroll
        for (int nt = 0; nt < 8; nt++) {
            float bb0 = sb2[nt * 8 + q], bb1 = sb2[nt * 8 + q + 1];
            D2[nt][0] = bb0; D2[nt][1] = bb1; D2[nt][2] = bb0; D2[nt][3] = bb1;
            #pragma unroll
            for (int kf = 0; kf < 2; kf++)
                mma3(D2[nt], A2h[kf], A2l[kf], sB2[nt * 2 + kf][lane]);
        }

        uint32_t A3h[4][4], A3l[4][4];
        #pragma unroll
        for (int kf = 0; kf < 4; kf++) {
            int na = 2 * kf, nb = 2 * kf + 1;
            float sa0 = silu_f(D2[na][0]), sa1 = silu_f(D2[na][1]);
            float sa2 = silu_f(D2[na][2]), sa3 = silu_f(D2[na][3]);
            float sb0 = silu_f(D2[nb][0]), sb1v = silu_f(D2[nb][1]);
            float sb2v = silu_f(D2[nb][2]), sb3v = silu_f(D2[nb][3]);
            pack_hl(sa0, sa1, A3h[kf][0], A3l[kf][0]);
            pack_hl(sa2, sa3, A3h[kf][1], A3l[kf][1]);
            pack_hl(sb0, sb1v, A3h[kf][2], A3l[kf][2]);
            pack_hl(sb2v, sb3v, A3h[kf][3], A3l[kf][3]);
        }

        float D3[12][4];
        #pragma unroll
        for (int nt = 0; nt < 12; nt++) {
            float bb0 = sb3[nt * 8 + q], bb1 = sb3[nt * 8 + q + 1];
            D3[nt][0] = bb0; D3[nt][1] = bb1; D3[nt][2] = bb0; D3[nt][3] = bb1;
            #pragma unroll
            for (int kf = 0; kf < 4; kf++)
                mma3(D3[nt], A3h[kf], A3l[kf], sB3[nt * 4 + kf][lane]);
        }

        // ---- epilogue: silu*Cc, pair lanes -> red.v4 scatter ----
        float wA = edge_weight[eAc], wB = edge_weight[eBc];
        float CcA = (wA < CUTOFF_F)
                  ? 0.5f * (__cosf(wA * (PI_F / CUTOFF_F)) + 1.0f) : 0.0f;
        float CcB = (wB < CUTOFF_F)
                  ? 0.5f * (__cosf(wB * (PI_F / CUTOFF_F)) + 1.0f) : 0.0f;
        int dA = edge_index[E + eAc], dB = edge_index[E + eBc];
        bool okA = eA < E, okB = eB < E;

        int colbase = (tig >> 1) << 2;
        bool isEven = (tig & 1) == 0;
        float* gP = g_acc + (isEven ? (size_t)dA : (size_t)dB) * 96 + colbase;
        bool ok = isEven ? okA : okB;

        #pragma unroll
        for (int nt = 0; nt < 12; nt++) {
            float t0 = silu_f(D3[nt][0]) * CcA;
            float t1 = silu_f(D3[nt][1]) * CcA;
            float t2 = silu_f(D3[nt][2]) * CcB;
            float t3 = silu_f(D3[nt][3]) * CcB;
            float p0 = __shfl_xor_sync(0xFFFFFFFFu, t0, 1);
            float p1 = __shfl_xor_sync(0xFFFFFFFFu, t1, 1);
            float p2 = __shfl_xor_sync(0xFFFFFFFFu, t2, 1);
            float p3 = __shfl_xor_sync(0xFFFFFFFFu, t3, 1);
            float v0 = isEven ? t0 : p2;
            float v1 = isEven ? t1 : p3;
            float v2 = isEven ? p0 : t2;
            float v3 = isEven ? p1 : t3;
            if (ok) {
                asm volatile("red.global.add.v4.f32 [%0], {%1, %2, %3, %4};"
                             :: "l"(gP + nt * 8),
                                "f"(v0), "f"(v1), "f"(v2), "f"(v3) : "memory");
            }
        }
    }
}

// ---------------------------------------------------------------------------
// Node kernel, MMA mixing, in-place c/r buffer.
#define RS 36   // row stride in floats

__global__ void __launch_bounds__(256)
node_mma_kernel(const float* __restrict__ X,
                const float* __restrict__ Wt,
                float* __restrict__ out,
                int nNodes, int nStrips)
{
    extern __shared__ char smem[];
    uint4* sB  = (uint4*)smem;                 // [mat*256 + f*32 + l], {h0,h1,l0,l1}
    float* cr  = (float*)(smem + 24576);

    const int tid  = threadIdx.x;
    const int lane = tid & 31, wid = tid >> 5;
    const int gr   = lane >> 2, tig = lane & 3;

    for (int i = tid; i < 1536; i += 256) {
        int mat = i >> 8, rem = i & 255;
        int f = rem >> 5, l = rem & 31;
        int nt = f >> 1, kf = f & 1;
        int n = nt * 8 + (l >> 2), k0 = kf * 16 + ((l & 3) << 1);
        const float* Wr = Wt + mat * 1024 + n * 32 + k0;
        uint32_t h0, l0, h1, l1;
        pack_hl(Wr[0], Wr[1], h0, l0);
        pack_hl(Wr[8], Wr[9], h1, l1);
        sB[i] = make_uint4(h0, h1, l0, l1);
    }
    __syncthreads();

    const int nl0 = tid >> 5;
    const int u   = lane;

    for (int s = blockIdx.x; s < nStrips; s += gridDim.x) {
        const int nodeBase = s << 4;
        float Xn[2][9];

        #pragma unroll
        for (int cc = 0; cc < 2; cc++) {
            int r0 = nl0 + cc * 8;
            int n  = nodeBase + r0;
            int nc = min(n, nNodes - 1);
            float nrm = 1.0f;
            #pragma unroll
            for (int t = 0; t < 9; t++) {
                float v = X[((size_t)nc * 9 + t) * 32 + u];
                Xn[cc][t] = v; nrm += v * v;
            }
            float inv = __fdividef(1.0f, nrm);
            #pragma unroll
            for (int t = 0; t < 9; t++) Xn[cc][t] *= inv;

            const float* x = Xn[cc];
            float tr3 = (x[0] + x[4] + x[8]) * (1.0f / 3.0f);
            float* cp = cr + r0 * RS + u;
            cp[0 * 16 * RS] = tr3;
            cp[1 * 16 * RS] = 0.5f * (x[1] - x[3]);
            cp[2 * 16 * RS] = 0.5f * (x[2] - x[6]);
            cp[3 * 16 * RS] = 0.5f * (x[5] - x[7]);
            cp[4 * 16 * RS] = x[0] - tr3;
            cp[5 * 16 * RS] = 0.5f * (x[1] + x[3]);
            cp[6 * 16 * RS] = 0.5f * (x[2] + x[6]);
            cp[7 * 16 * RS] = x[4] - tr3;
            cp[8 * 16 * RS] = 0.5f * (x[5] + x[7]);
        }
        __syncthreads();

        #pragma unroll 1
        for (int rt = wid; rt < 9; rt += 8) {
            int mat = (rt == 0) ? 0 : (rt < 4) ? 1 : 2;
            const float* crow0 = cr + (16 * rt + gr) * RS;
            const float* crow1 = crow0 + 8 * RS;
            uint32_t Ah[2][4], Al[2][4];
            #pragma unroll
            for (int kf = 0; kf < 2; kf++) {
                int c0 = kf * 16 + 2 * tig;
                float2 v0 = *(const float2*)(crow0 + c0);
                float2 v1 = *(const float2*)(crow1 + c0);
                float2 v2 = *(const float2*)(crow0 + c0 + 8);
                float2 v3 = *(const float2*)(crow1 + c0 + 8);
                pack_hl(v0.x, v0.y, Ah[kf][0], Al[kf][0]);
                pack_hl(v1.x, v1.y, Ah[kf][1], Al[kf][1]);
                pack_hl(v2.x, v2.y, Ah[kf][2], Al[kf][2]);
                pack_hl(v3.x, v3.y, Ah[kf][3], Al[kf][3]);
            }
            float D[4][4];
            #pragma unroll
            for (int nt = 0; nt < 4; nt++) {
                D[nt][0] = 0.f; D[nt][1] = 0.f; D[nt][2] = 0.f; D[nt][3] = 0.f;
                #pragma unroll
                for (int kf = 0; kf < 2; kf++)
                    mma3(D[nt], Ah[kf], Al[kf], sB[mat * 256 + (nt * 2 + kf) * 32 + lane]);
            }
            float* wr0 = cr + (16 * rt + gr) * RS + 2 * tig;
            float* wr1 = wr0 + 8 * RS;
            #pragma unroll
            for (int nt = 0; nt < 4; nt++) {
                *(float2*)(wr0 + nt * 8) = make_float2(D[nt][0], D[nt][1]);
                *(float2*)(wr1 + nt * 8) = make_float2(D[nt][2], D[nt][3]);
            }
        }
        __syncthreads();

        #pragma unroll
        for (int cc = 0; cc < 2; cc++) {
            int r0 = nl0 + cc * 8;
            int n  = nodeBase + r0;
            float* rp = cr + r0 * RS + u;
            float Ip  = rp[0 * 16 * RS];
            float a01 = rp[1 * 16 * RS];
            float a02 = rp[2 * 16 * RS];
            float a12 = rp[3 * 16 * RS];
            float s00 = rp[4 * 16 * RS];
            float s01 = rp[5 * 16 * RS];
            float s02 = rp[6 * 16 * RS];
            float s11 = rp[7 * 16 * RS];
            float s12 = rp[8 * 16 * RS];
            float s22 = -(s00 + s11);

            float sI = 0.f, sA = 0.f, sS = 0.f;
            if (n < nNodes) {
                float* ap = g_acc + (size_t)n * 96 + u * 3;
                sI = ap[0]; sA = ap[1]; sS = ap[2];
                ap[0] = 0.f; ap[1] = 0.f; ap[2] = 0.f;
            }

            float Y[9], G[9];
            Y[0] = Ip + s00;  Y[1] = a01 + s01;  Y[2] = a02 + s02;
            Y[3] = s01 - a01; Y[4] = Ip + s11;   Y[5] = a12 + s12;
            Y[6] = s02 - a02; Y[7] = s12 - a12;  Y[8] = Ip + s22;
            G[0] = Ip*sI + s00*sS;  G[1] = a01*sA + s01*sS;  G[2] = a02*sA + s02*sS;
            G[3] = s01*sS - a01*sA; G[4] = Ip*sI + s11*sS;   G[5] = a12*sA + s12*sS;
            G[6] = s02*sS - a02*sA; G[7] = s12*sS - a12*sA;  G[8] = Ip*sI + s22*sS;

            float M[9];
            #pragma unroll
            for (int i = 0; i < 3; i++)
                #pragma unroll
                for (int l = 0; l < 3; l++) {
                    float a2 = 0.0f;
                    #pragma unroll
                    for (int j = 0; j < 3; j++)
                        a2 += Y[i*3+j] * G[j*3+l] + G[i*3+j] * Y[j*3+l];
                    M[i*3+l] = a2;
                }

            float np = 1.0f;
            #pragma unroll
            for (int t = 0; t < 9; t++) np += M[t] * M[t];
            float inv2 = __fdividef(1.0f, np);
            float trm = (M[0] + M[4] + M[8]) * (1.0f / 3.0f);

            rp[0 * 16 * RS] = trm * inv2;
            rp[1 * 16 * RS] = 0.5f * (M[1] - M[3]) * inv2;
            rp[2 * 16 * RS] = 0.5f * (M[2] - M[6]) * inv2;
            rp[3 * 16 * RS] = 0.5f * (M[5] - M[7]) * inv2;
            rp[4 * 16 * RS] = (M[0] - trm) * inv2;
            rp[5 * 16 * RS] = 0.5f * (M[1] + M[3]) * inv2;
            rp[6 * 16 * RS] = 0.5f * (M[2] + M[6]) * inv2;
            rp[7 * 16 * RS] = (M[4] - trm) * inv2;
            rp[8 * 16 * RS] = 0.5f * (M[5] + M[7]) * inv2;
        }
        __syncthreads();

        #pragma unroll 1
        for (int rt = wid; rt < 9; rt += 8) {
            int mat = 3 + ((rt == 0) ? 0 : (rt < 4) ? 1 : 2);
            const float* crow0 = cr + (16 * rt + gr) * RS;
            const float* crow1 = crow0 + 8 * RS;
            uint32_t Ah[2][4], Al[2][4];
            #pragma unroll
            for (int kf = 0; kf < 2; kf++) {
                int c0 = kf * 16 + 2 * tig;
                float2 v0 = *(const float2*)(crow0 + c0);
                float2 v1 = *(const float2*)(crow1 + c0);
                float2 v2 = *(const float2*)(crow0 + c0 + 8);
                float2 v3 = *(const float2*)(crow1 + c0 + 8);
                pack_hl(v0.x, v0.y, Ah[kf][0], Al[kf][0]);
                pack_hl(v1.x, v1.y, Ah[kf][1], Al[kf][1]);
                pack_hl(v2.x, v2.y, Ah[kf][2], Al[kf][2]);
                pack_hl(v3.x, v3.y, Ah[kf][3], Al[kf][3]);
            }
            float D[4][4];
            #pragma unroll
            for (int nt = 0; nt < 4; nt++) {
                D[nt][0] = 0.f; D[nt][1] = 0.f; D[nt][2] = 0.f; D[nt][3] = 0.f;
                #pragma unroll
                for (int kf = 0; kf < 2; kf++)
                    mma3(D[nt], Ah[kf], Al[kf], sB[mat * 256 + (nt * 2 + kf) * 32 + lane]);
            }
            float* wr0 = cr + (16 * rt + gr) * RS + 2 * tig;
            float* wr1 = wr0 + 8 * RS;
            #pragma unroll
            for (int nt = 0; nt < 4; nt++) {
                *(float2*)(wr0 + nt * 8) = make_float2(D[nt][0], D[nt][1]);
                *(float2*)(wr1 + nt * 8) = make_float2(D[nt][2], D[nt][3]);
            }
        }
        __syncthreads();

        #pragma unroll
        for (int cc = 0; cc < 2; cc++) {
            int r0 = nl0 + cc * 8;
            int n  = nodeBase + r0;
            const float* rp = cr + r0 * RS + u;
            float Ip2 = rp[0 * 16 * RS];
            float b01 = rp[1 * 16 * RS];
            float b02 = rp[2 * 16 * RS];
            float b12 = rp[3 * 16 * RS];
            float t00 = rp[4 * 16 * RS];
            float t01 = rp[5 * 16 * RS];
            float t02 = rp[6 * 16 * RS];
            float t11 = rp[7 * 16 * RS];
            float t12 = rp[8 * 16 * RS];
            float t22 = -(t00 + t11);

            float D[9];
            D[0] = Ip2 + t00;  D[1] = b01 + t01;  D[2] = b02 + t02;
            D[3] = t01 - b01;  D[4] = Ip2 + t11;  D[5] = b12 + t12;
            D[6] = t02 - b02;  D[7] = t12 - b12;  D[8] = Ip2 + t22;

            if (n < nNodes) {
                #pragma unroll
                for (int i = 0; i < 3; i++)
                    #pragma unroll
                    for (int l = 0; l < 3; l++) {
                        float o = Xn[cc][i*3+l] + D[i*3+l];
                        #pragma unroll
                        for (int j = 0; j < 3; j++)
                            o += D[i*3+j] * D[j*3+l];
                        out[((size_t)n * 9 + (i*3+l)) * 32 + u] = o;
                    }
            }
        }
        __syncthreads();
    }
}

// ---------------------------------------------------------------------------
extern "C" void kernel_launch(void* const* d_in, const int* in_sizes, int n_in,
                              void* d_out, int out_size)
{
    const float* X           = (const float*)d_in[0];
    const int*   edge_index  = (const int*)  d_in[1];
    const float* edge_weight = (const float*)d_in[2];
    const float* edge_attr   = (const float*)d_in[3];
    const float* W1 = (const float*)d_in[4];
    const float* b1 = (const float*)d_in[5];
    const float* W2 = (const float*)d_in[6];
    const float* b2 = (const float*)d_in[7];
    const float* W3 = (const float*)d_in[8];
    const float* b3 = (const float*)d_in[9];
    const float* Wt = (const float*)d_in[10];
    float* out = (float*)d_out;

    int N = in_sizes[0] / 288;   // X is (N,3,3,32)
    if (N > MAXN) N = MAXN;
    int E = in_sizes[2];         // edge_weight is (E,)

    int nStrips = (E + 15) >> 4;
    int grid = (nStrips + 7) / 8;
    if (grid > 296) grid = 296;

    edge_mma_kernel<<<grid, 256>>>(
        edge_attr, edge_index, edge_weight, W1, b1, W2, b2, W3, b3, E);

    int nodeSmem = 24576 + 144 * RS * 4;   // 45312 bytes
    static bool attr_set = false;
    if (!attr_set) {
        cudaFuncSetAttribute(node_mma_kernel,
                             cudaFuncAttributeMaxDynamicSharedMemorySize, nodeSmem);
        attr_set = true;
    }
    int nodeStrips = (N + 15) / 16;
    int nodeGrid = nodeStrips < 592 ? nodeStrips : 592;
    node_mma_kernel<<<nodeGrid, 256, nodeSmem>>>(X, Wt, out, N, nodeStrips);
}

// round 11
// speedup vs baseline: 1.1324x; 1.1324x over previous
#include <cuda_runtime.h>
#include <cuda_bf16.h>
#include <cstdint>

// ---------------------------------------------------------------------------
// TensorNet interaction.
//   msg[n] = (component tensors of n) * (per-node scalar sums of edge MLP),
//   so the graph part is a scatter-add of 96 edge-MLP outputs into acc[n][96].
//
// R11: recombination of per-kernel winners measured in R8-R10:
//   edge  = R10 variant (__launch_bounds__(256,2), uint4 B-frags/LDS.128,
//           lane-paired red.v4 scatter)  -> ~62us measured
//   node  = R8 variant  (uint2 Bh/Bl split loads, in-place cr buffer)
//           -> 66.7us measured (uint4 there REGRESSED to 94us: LDS.128
//           latency lands on the sync-fenced critical path)
// ---------------------------------------------------------------------------

#define MAXN 50000
#define PI_F 3.14159265358979323846f
#define CUTOFF_F 5.0f

__device__ float g_acc[(size_t)MAXN * 96];

__device__ __forceinline__ float silu_f(float v) {
    return v * __fdividef(1.0f, 1.0f + __expf(-v));
}
__device__ __forceinline__ uint32_t packbf(float lo, float hi) {
    uint32_t r;
    asm("cvt.rn.bf16x2.f32 %0, %1, %2;" : "=r"(r) : "f"(hi), "f"(lo));
    return r;
}
__device__ __forceinline__ float bf16val(float v) {
    return __bfloat162float(__float2bfloat16(v));
}
__device__ __forceinline__ void pack_hl(float x, float y, uint32_t& h, uint32_t& l) {
    h = packbf(x, y);
    l = packbf(x - bf16val(x), y - bf16val(y));
}
__device__ __forceinline__ void mma_bf16r(float c[4], const uint32_t a[4], uint32_t bx, uint32_t by) {
    asm volatile(
        "mma.sync.aligned.m16n8k16.row.col.f32.bf16.bf16.f32 "
        "{%0,%1,%2,%3}, {%4,%5,%6,%7}, {%8,%9}, {%0,%1,%2,%3};"
        : "+f"(c[0]), "+f"(c[1]), "+f"(c[2]), "+f"(c[3])
        : "r"(a[0]), "r"(a[1]), "r"(a[2]), "r"(a[3]), "r"(bx), "r"(by));
}
__device__ __forceinline__ void mma_bf16(float c[4], const uint32_t a[4], uint2 b) {
    mma_bf16r(c, a, b.x, b.y);
}
// one LDS.128 fragment: {h0,h1,l0,l1}; issue 3-term split
__device__ __forceinline__ void mma3(float c[4], const uint32_t ah[4],
                                     const uint32_t al[4], uint4 B) {
    mma_bf16r(c, ah, B.x, B.y);
    mma_bf16r(c, al, B.x, B.y);
    mma_bf16r(c, ah, B.z, B.w);
}

// ---------------------------------------------------------------------------
// Edge MLP kernel (R10 variant). Warp = 16-edge strip.
__global__ void __launch_bounds__(256, 2)
edge_mma_kernel(const float* __restrict__ edge_attr,
                const int*   __restrict__ edge_index,
                const float* __restrict__ edge_weight,
                const float* __restrict__ W1, const float* __restrict__ b1,
                const float* __restrict__ W2, const float* __restrict__ b2,
                const float* __restrict__ W3, const float* __restrict__ b3,
                int E)
{
    __shared__ uint4 sB1[8][32];    // {h0,h1,l0,l1}
    __shared__ uint4 sB2[16][32];
    __shared__ uint4 sB3[48][32];
    __shared__ float sb1[32], sb2[64], sb3[96];

    const int tid = threadIdx.x;

    {
        int i = tid;
        int f = i >> 5, l = i & 31;
        int nt = f >> 1, kf = f & 1;
        int n = nt * 8 + (l >> 2), k0 = kf * 16 + ((l & 3) << 1);
        const float* Wr = W1 + n * 32 + k0;
        uint32_t h0, l0, h1, l1;
        pack_hl(Wr[0], Wr[1], h0, l0);
        pack_hl(Wr[8], Wr[9], h1, l1);
        sB1[f][l] = make_uint4(h0, h1, l0, l1);
    }
    for (int i = tid; i < 512; i += 256) {
        int f = i >> 5, l = i & 31;
        int nt = f >> 1, kf = f & 1;
        int n = nt * 8 + (l >> 2), k0 = kf * 16 + ((l & 3) << 1);
        const float* Wr = W2 + n * 32 + k0;
        uint32_t h0, l0, h1, l1;
        pack_hl(Wr[0], Wr[1], h0, l0);
        pack_hl(Wr[8], Wr[9], h1, l1);
        sB2[f][l] = make_uint4(h0, h1, l0, l1);
    }
    for (int i = tid; i < 1536; i += 256) {
        int f = i >> 5, l = i & 31;
        int nt = f >> 2, kf = f & 3;
        int n = nt * 8 + (l >> 2), k0 = kf * 16 + ((l & 3) << 1);
        const float* Wr = W3 + n * 64 + k0;
        uint32_t h0, l0, h1, l1;
        pack_hl(Wr[0], Wr[1], h0, l0);
        pack_hl(Wr[8], Wr[9], h1, l1);
        sB3[f][l] = make_uint4(h0, h1, l0, l1);
    }
    if (tid < 32) sb1[tid] = b1[tid];
    if (tid < 64) sb2[tid] = b2[tid];
    if (tid < 96) sb3[tid] = b3[tid];
    __syncthreads();

    const int wid = tid >> 5, lane = tid & 31;
    const int r1 = lane >> 2;
    const int tig = lane & 3;
    const int q  = tig << 1;
    const int nStrips = (E + 15) >> 4;

    for (int strip = blockIdx.x * 8 + wid; strip < nStrips;
         strip += gridDim.x * 8) {
        int e0 = strip << 4;
        int eA = e0 + r1, eB = eA + 8;
        int eAc = min(eA, E - 1), eBc = min(eB, E - 1);

        uint32_t A1h[2][4], A1l[2][4];
        #pragma unroll
        for (int kf = 0; kf < 2; kf++) {
            const float* pa = edge_attr + (size_t)eAc * 32 + kf * 16 + q;
            const float* pb = edge_attr + (size_t)eBc * 32 + kf * 16 + q;
            float2 v0 = *(const float2*)pa;
            float2 v1 = *(const float2*)pb;
            float2 v2 = *(const float2*)(pa + 8);
            float2 v3 = *(const float2*)(pb + 8);
            pack_hl(v0.x, v0.y, A1h[kf][0], A1l[kf][0]);
            pack_hl(v1.x, v1.y, A1h[kf][1], A1l[kf][1]);
            pack_hl(v2.x, v2.y, A1h[kf][2], A1l[kf][2]);
            pack_hl(v3.x, v3.y, A1h[kf][3], A1l[kf][3]);
        }

        float D1[4][4];
        #pragma unroll
        for (int nt = 0; nt < 4; nt++) {
            float bb0 = sb1[nt * 8 + q], bb1 = sb1[nt * 8 + q + 1];
            D1[nt][0] = bb0; D1[nt][1] = bb1; D1[nt][2] = bb0; D1[nt][3] = bb1;
            #pragma unroll
            for (int kf = 0; kf < 2; kf++)
                mma3(D1[nt], A1h[kf], A1l[kf], sB1[nt * 2 + kf][lane]);
        }

        uint32_t A2h[2][4], A2l[2][4];
        #pragma unroll
        for (int kf = 0; kf < 2; kf++) {
            int na = 2 * kf, nb = 2 * kf + 1;
            float sa0 = silu_f(D1[na][0]), sa1 = silu_f(D1[na][1]);
            float sa2 = silu_f(D1[na][2]), sa3 = silu_f(D1[na][3]);
            float sb0 = silu_f(D1[nb][0]), sb1v = silu_f(D1[nb][1]);
            float sb2v = silu_f(D1[nb][2]), sb3v = silu_f(D1[nb][3]);
            pack_hl(sa0, sa1, A2h[kf][0], A2l[kf][0]);
            pack_hl(sa2, sa3, A2h[kf][1], A2l[kf][1]);
            pack_hl(sb0, sb1v, A2h[kf][2], A2l[kf][2]);
            pack_hl(sb2v, sb3v, A2h[kf][3], A2l[kf][3]);
        }

        float D2[8][4];
        #pragma unroll
        for (int nt = 0; nt < 8; nt++) {
            float bb0 = sb2[nt * 8 + q], bb1 = sb2[nt * 8 + q + 1];
            D2[nt][0] = bb0; D2[nt][1] = bb1; D2[nt][2] = bb0; D2[nt][3] = bb1;
            #pragma unroll
            for (int kf = 0; kf < 2; kf++)
                mma3(D2[nt], A2h[kf], A2l[kf], sB2[nt * 2 + kf][lane]);
        }

        uint32_t A3h[4][4], A3l[4][4];
        #pragma unroll
        for (int kf = 0; kf < 4; kf++) {
            int na = 2 * kf, nb = 2 * kf + 1;
            float sa0 = silu_f(D2[na][0]), sa1 = silu_f(D2[na][1]);
            float sa2 = silu_f(D2[na][2]), sa3 = silu_f(D2[na][3]);
            float sb0 = silu_f(D2[nb][0]), sb1v = silu_f(D2[nb][1]);
            float sb2v = silu_f(D2[nb][2]), sb3v = silu_f(D2[nb][3]);
            pack_hl(sa0, sa1, A3h[kf][0], A3l[kf][0]);
            pack_hl(sa2, sa3, A3h[kf][1], A3l[kf][1]);
            pack_hl(sb0, sb1v, A3h[kf][2], A3l[kf][2]);
            pack_hl(sb2v, sb3v, A3h[kf][3], A3l[kf][3]);
        }

        float D3[12][4];
        #pragma unroll
        for (int nt = 0; nt < 12; nt++) {
            float bb0 = sb3[nt * 8 + q], bb1 = sb3[nt * 8 + q + 1];
            D3[nt][0] = bb0; D3[nt][1] = bb1; D3[nt][2] = bb0; D3[nt][3] = bb1;
            #pragma unroll
            for (int kf = 0; kf < 4; kf++)
                mma3(D3[nt], A3h[kf], A3l[kf], sB3[nt * 4 + kf][lane]);
        }

        // ---- epilogue: silu*Cc, pair lanes -> red.v4 scatter ----
        float wA = edge_weight[eAc], wB = edge_weight[eBc];
        float CcA = (wA < CUTOFF_F)
                  ? 0.5f * (__cosf(wA * (PI_F / CUTOFF_F)) + 1.0f) : 0.0f;
        float CcB = (wB < CUTOFF_F)
                  ? 0.5f * (__cosf(wB * (PI_F / CUTOFF_F)) + 1.0f) : 0.0f;
        int dA = edge_index[E + eAc], dB = edge_index[E + eBc];
        bool okA = eA < E, okB = eB < E;

        int colbase = (tig >> 1) << 2;
        bool isEven = (tig & 1) == 0;
        float* gP = g_acc + (isEven ? (size_t)dA : (size_t)dB) * 96 + colbase;
        bool ok = isEven ? okA : okB;

        #pragma unroll
        for (int nt = 0; nt < 12; nt++) {
            float t0 = silu_f(D3[nt][0]) * CcA;
            float t1 = silu_f(D3[nt][1]) * CcA;
            float t2 = silu_f(D3[nt][2]) * CcB;
            float t3 = silu_f(D3[nt][3]) * CcB;
            float p0 = __shfl_xor_sync(0xFFFFFFFFu, t0, 1);
            float p1 = __shfl_xor_sync(0xFFFFFFFFu, t1, 1);
            float p2 = __shfl_xor_sync(0xFFFFFFFFu, t2, 1);
            float p3 = __shfl_xor_sync(0xFFFFFFFFu, t3, 1);
            float v0 = isEven ? t0 : p2;
            float v1 = isEven ? t1 : p3;
            float v2 = isEven ? p0 : t2;
            float v3 = isEven ? p1 : t3;
            if (ok) {
                asm volatile("red.global.add.v4.f32 [%0], {%1, %2, %3, %4};"
                             :: "l"(gP + nt * 8),
                                "f"(v0), "f"(v1), "f"(v2), "f"(v3) : "memory");
            }
        }
    }
}

// ---------------------------------------------------------------------------
// Node kernel (R8 variant): MMA mixing, uint2 split B-frags, in-place cr.
#define RS 36   // row stride in floats

__global__ void __launch_bounds__(256)
node_mma_kernel(const float* __restrict__ X,
                const float* __restrict__ Wt,
                float* __restrict__ out,
                int nNodes, int nStrips)
{
    extern __shared__ char smem[];
    uint2* sBh  = (uint2*)smem;                       // [mat*256 + f*32 + l]
    uint2* sBl  = (uint2*)(smem + 12288);
    float* cr   = (float*)(smem + 24576);             // [144][RS]

    const int tid  = threadIdx.x;
    const int lane = tid & 31, wid = tid >> 5;
    const int gr   = lane >> 2, tig = lane & 3;

    for (int i = tid; i < 1536; i += 256) {
        int mat = i >> 8, rem = i & 255;
        int f = rem >> 5, l = rem & 31;
        int nt = f >> 1, kf = f & 1;
        int n = nt * 8 + (l >> 2), k0 = kf * 16 + ((l & 3) << 1);
        const float* Wr = Wt + mat * 1024 + n * 32 + k0;
        uint32_t h0, l0, h1, l1;
        pack_hl(Wr[0], Wr[1], h0, l0);
        pack_hl(Wr[8], Wr[9], h1, l1);
        sBh[i] = make_uint2(h0, h1);
        sBl[i] = make_uint2(l0, l1);
    }
    __syncthreads();

    const int nl0 = tid >> 5;
    const int u   = lane;

    for (int s = blockIdx.x; s < nStrips; s += gridDim.x) {
        const int nodeBase = s << 4;
        float Xn[2][9];

        #pragma unroll
        for (int cc = 0; cc < 2; cc++) {
            int r0 = nl0 + cc * 8;
            int n  = nodeBase + r0;
            int nc = min(n, nNodes - 1);
            float nrm = 1.0f;
            #pragma unroll
            for (int t = 0; t < 9; t++) {
                float v = X[((size_t)nc * 9 + t) * 32 + u];
                Xn[cc][t] = v; nrm += v * v;
            }
            float inv = __fdividef(1.0f, nrm);
            #pragma unroll
            for (int t = 0; t < 9; t++) Xn[cc][t] *= inv;

            const float* x = Xn[cc];
            float tr3 = (x[0] + x[4] + x[8]) * (1.0f / 3.0f);
            float* cp = cr + r0 * RS + u;
            cp[0 * 16 * RS] = tr3;
            cp[1 * 16 * RS] = 0.5f * (x[1] - x[3]);
            cp[2 * 16 * RS] = 0.5f * (x[2] - x[6]);
            cp[3 * 16 * RS] = 0.5f * (x[5] - x[7]);
            cp[4 * 16 * RS] = x[0] - tr3;
            cp[5 * 16 * RS] = 0.5f * (x[1] + x[3]);
            cp[6 * 16 * RS] = 0.5f * (x[2] + x[6]);
            cp[7 * 16 * RS] = x[4] - tr3;
            cp[8 * 16 * RS] = 0.5f * (x[5] + x[7]);
        }
        __syncthreads();

        #pragma unroll 1
        for (int rt = wid; rt < 9; rt += 8) {
            int mat = (rt == 0) ? 0 : (rt < 4) ? 1 : 2;
            const float* crow0 = cr + (16 * rt + gr) * RS;
            const float* crow1 = crow0 + 8 * RS;
            uint32_t Ah[2][4], Al[2][4];
            #pragma unroll
            for (int kf = 0; kf < 2; kf++) {
                int c0 = kf * 16 + 2 * tig;
                float2 v0 = *(const float2*)(crow0 + c0);
                float2 v1 = *(const float2*)(crow1 + c0);
                float2 v2 = *(const float2*)(crow0 + c0 + 8);
                float2 v3 = *(const float2*)(crow1 + c0 + 8);
                pack_hl(v0.x, v0.y, Ah[kf][0], Al[kf][0]);
                pack_hl(v1.x, v1.y, Ah[kf][1], Al[kf][1]);
                pack_hl(v2.x, v2.y, Ah[kf][2], Al[kf][2]);
                pack_hl(v3.x, v3.y, Ah[kf][3], Al[kf][3]);
            }
            float D[4][4];
            #pragma unroll
            for (int nt = 0; nt < 4; nt++) {
                D[nt][0] = 0.f; D[nt][1] = 0.f; D[nt][2] = 0.f; D[nt][3] = 0.f;
                #pragma unroll
                for (int kf = 0; kf < 2; kf++) {
                    uint2 Bh = sBh[mat * 256 + (nt * 2 + kf) * 32 + lane];
                    uint2 Bl = sBl[mat * 256 + (nt * 2 + kf) * 32 + lane];
                    mma_bf16(D[nt], Ah[kf], Bh);
                    mma_bf16(D[nt], Al[kf], Bh);
                    mma_bf16(D[nt], Ah[kf], Bl);
                }
            }
            float* wr0 = cr + (16 * rt + gr) * RS + 2 * tig;
            float* wr1 = wr0 + 8 * RS;
            #pragma unroll
            for (int nt = 0; nt < 4; nt++) {
                *(float2*)(wr0 + nt * 8) = make_float2(D[nt][0], D[nt][1]);
                *(float2*)(wr1 + nt * 8) = make_float2(D[nt][2], D[nt][3]);
            }
        }
        __syncthreads();

        #pragma unroll
        for (int cc = 0; cc < 2; cc++) {
            int r0 = nl0 + cc * 8;
            int n  = nodeBase + r0;
            float* rp = cr + r0 * RS + u;
            float Ip  = rp[0 * 16 * RS];
            float a01 = rp[1 * 16 * RS];
            float a02 = rp[2 * 16 * RS];
            float a12 = rp[3 * 16 * RS];
            float s00 = rp[4 * 16 * RS];
            float s01 = rp[5 * 16 * RS];
            float s02 = rp[6 * 16 * RS];
            float s11 = rp[7 * 16 * RS];
            float s12 = rp[8 * 16 * RS];
            float s22 = -(s00 + s11);

            float sI = 0.f, sA = 0.f, sS = 0.f;
            if (n < nNodes) {
                float* ap = g_acc + (size_t)n * 96 + u * 3;
                sI = ap[0]; sA = ap[1]; sS = ap[2];
                ap[0] = 0.f; ap[1] = 0.f; ap[2] = 0.f;
            }

            float Y[9], G[9];
            Y[0] = Ip + s00;  Y[1] = a01 + s01;  Y[2] = a02 + s02;
            Y[3] = s01 - a01; Y[4] = Ip + s11;   Y[5] = a12 + s12;
            Y[6] = s02 - a02; Y[7] = s12 - a12;  Y[8] = Ip + s22;
            G[0] = Ip*sI + s00*sS;  G[1] = a01*sA + s01*sS;  G[2] = a02*sA + s02*sS;
            G[3] = s01*sS - a01*sA; G[4] = Ip*sI + s11*sS;   G[5] = a12*sA + s12*sS;
            G[6] = s02*sS - a02*sA; G[7] = s12*sS - a12*sA;  G[8] = Ip*sI + s22*sS;

            float M[9];
            #pragma unroll
            for (int i = 0; i < 3; i++)
                #pragma unroll
                for (int l = 0; l < 3; l++) {
                    float a2 = 0.0f;
                    #pragma unroll
                    for (int j = 0; j < 3; j++)
                        a2 += Y[i*3+j] * G[j*3+l] + G[i*3+j] * Y[j*3+l];
                    M[i*3+l] = a2;
                }

            float np = 1.0f;
            #pragma unroll
            for (int t = 0; t < 9; t++) np += M[t] * M[t];
            float inv2 = __fdividef(1.0f, np);
            float trm = (M[0] + M[4] + M[8]) * (1.0f / 3.0f);

            rp[0 * 16 * RS] = trm * inv2;
            rp[1 * 16 * RS] = 0.5f * (M[1] - M[3]) * inv2;
            rp[2 * 16 * RS] = 0.5f * (M[2] - M[6]) * inv2;
            rp[3 * 16 * RS] = 0.5f * (M[5] - M[7]) * inv2;
            rp[4 * 16 * RS] = (M[0] - trm) * inv2;
            rp[5 * 16 * RS] = 0.5f * (M[1] + M[3]) * inv2;
            rp[6 * 16 * RS] = 0.5f * (M[2] + M[6]) * inv2;
            rp[7 * 16 * RS] = (M[4] - trm) * inv2;
            rp[8 * 16 * RS] = 0.5f * (M[5] + M[7]) * inv2;
        }
        __syncthreads();

        #pragma unroll 1
        for (int rt = wid; rt < 9; rt += 8) {
            int mat = 3 + ((rt == 0) ? 0 : (rt < 4) ? 1 : 2);
            const float* crow0 = cr + (16 * rt + gr) * RS;
            const float* crow1 = crow0 + 8 * RS;
            uint32_t Ah[2][4], Al[2][4];
            #pragma unroll
            for (int kf = 0; kf < 2; kf++) {
                int c0 = kf * 16 + 2 * tig;
                float2 v0 = *(const float2*)(crow0 + c0);
                float2 v1 = *(const float2*)(crow1 + c0);
                float2 v2 = *(const float2*)(crow0 + c0 + 8);
                float2 v3 = *(const float2*)(crow1 + c0 + 8);
                pack_hl(v0.x, v0.y, Ah[kf][0], Al[kf][0]);
                pack_hl(v1.x, v1.y, Ah[kf][1], Al[kf][1]);
                pack_hl(v2.x, v2.y, Ah[kf][2], Al[kf][2]);
                pack_hl(v3.x, v3.y, Ah[kf][3], Al[kf][3]);
            }
            float D[4][4];
            #pragma unroll
            for (int nt = 0; nt < 4; nt++) {
                D[nt][0] = 0.f; D[nt][1] = 0.f; D[nt][2] = 0.f; D[nt][3] = 0.f;
                #pragma unroll
                for (int kf = 0; kf < 2; kf++) {
                    uint2 Bh = sBh[mat * 256 + (nt * 2 + kf) * 32 + lane];
                    uint2 Bl = sBl[mat * 256 + (nt * 2 + kf) * 32 + lane];
                    mma_bf16(D[nt], Ah[kf], Bh);
                    mma_bf16(D[nt], Al[kf], Bh);
                    mma_bf16(D[nt], Ah[kf], Bl);
                }
            }
            float* wr0 = cr + (16 * rt + gr) * RS + 2 * tig;
            float* wr1 = wr0 + 8 * RS;
            #pragma unroll
            for (int nt = 0; nt < 4; nt++) {
                *(float2*)(wr0 + nt * 8) = make_float2(D[nt][0], D[nt][1]);
                *(float2*)(wr1 + nt * 8) = make_float2(D[nt][2], D[nt][3]);
            }
        }
        __syncthreads();

        #pragma unroll
        for (int cc = 0; cc < 2; cc++) {
            int r0 = nl0 + cc * 8;
            int n  = nodeBase + r0;
            const float* rp = cr + r0 * RS + u;
            float Ip2 = rp[0 * 16 * RS];
            float b01 = rp[1 * 16 * RS];
            float b02 = rp[2 * 16 * RS];
            float b12 = rp[3 * 16 * RS];
            float t00 = rp[4 * 16 * RS];
            float t01 = rp[5 * 16 * RS];
            float t02 = rp[6 * 16 * RS];
            float t11 = rp[7 * 16 * RS];
            float t12 = rp[8 * 16 * RS];
            float t22 = -(t00 + t11);

            float D[9];
            D[0] = Ip2 + t00;  D[1] = b01 + t01;  D[2] = b02 + t02;
            D[3] = t01 - b01;  D[4] = Ip2 + t11;  D[5] = b12 + t12;
            D[6] = t02 - b02;  D[7] = t12 - b12;  D[8] = Ip2 + t22;

            if (n < nNodes) {
                #pragma unroll
                for (int i = 0; i < 3; i++)
                    #pragma unroll
                    for (int l = 0; l < 3; l++) {
                        float o = Xn[cc][i*3+l] + D[i*3+l];
                        #pragma unroll
                        for (int j = 0; j < 3; j++)
                            o += D[i*3+j] * D[j*3+l];
                        out[((size_t)n * 9 + (i*3+l)) * 32 + u] = o;
                    }
            }
        }
        __syncthreads();
    }
}

// ---------------------------------------------------------------------------
extern "C" void kernel_launch(void* const* d_in, const int* in_sizes, int n_in,
                              void* d_out, int out_size)
{
    const float* X           = (const float*)d_in[0];
    const int*   edge_index  = (const int*)  d_in[1];
    const float* edge_weight = (const float*)d_in[2];
    const float* edge_attr   = (const float*)d_in[3];
    const float* W1 = (const float*)d_in[4];
    const float* b1 = (const float*)d_in[5];
    const float* W2 = (const float*)d_in[6];
    const float* b2 = (const float*)d_in[7];
    const float* W3 = (const float*)d_in[8];
    const float* b3 = (const float*)d_in[9];
    const float* Wt = (const float*)d_in[10];
    float* out = (float*)d_out;

    int N = in_sizes[0] / 288;   // X is (N,3,3,32)
    if (N > MAXN) N = MAXN;
    int E = in_sizes[2];         // edge_weight is (E,)

    int nStrips = (E + 15) >> 4;
    int grid = (nStrips + 7) / 8;
    if (grid > 296) grid = 296;

    edge_mma_kernel<<<grid, 256>>>(
        edge_attr, edge_index, edge_weight, W1, b1, W2, b2, W3, b3, E);

    int nodeSmem = 24576 + 144 * RS * 4;   // 45312 bytes
    static bool attr_set = false;
    if (!attr_set) {
        cudaFuncSetAttribute(node_mma_kernel,
                             cudaFuncAttributeMaxDynamicSharedMemorySize, nodeSmem);
        attr_set = true;
    }
    int nodeStrips = (N + 15) / 16;
    int nodeGrid = nodeStrips < 592 ? nodeStrips : 592;
    node_mma_kernel<<<nodeGrid, 256, nodeSmem>>>(X, Wt, out, N, nodeStrips);
}

// round 13
// speedup vs baseline: 1.1868x; 1.0480x over previous
#include <cuda_runtime.h>
#include <cuda_bf16.h>
#include <cstdint>

// ---------------------------------------------------------------------------
// TensorNet interaction.
//   msg[n] = (component tensors of n) * (per-node scalar sums of edge MLP),
//   so the graph part is a scatter-add of 96 edge-MLP outputs into acc[n][96].
//
// R12b (compile fix of R12):
//  * edge: silu via tanh.approx.f32 (1 MUFU instead of EX2+RCP) -- MUFU pipe
//    was the largest single term (~36us chip-wide). Costs ~1e-4 rel_err.
//  * node: GEMM load-balance. Each warp owns one rt tile; rt8's 4 n-tiles
//    spread one-each over warps 0-3, writing to rows 144-159 (no race).
// ---------------------------------------------------------------------------

#define MAXN 50000
#define PI_F 3.14159265358979323846f
#define CUTOFF_F 5.0f

__device__ float g_acc[(size_t)MAXN * 96];

// fast silu: v*sigmoid(v) = h + h*tanh(h), h = v/2   (1 MUFU)
__device__ __forceinline__ float silu_f(float v) {
    float h = 0.5f * v;
    float t;
    asm("tanh.approx.f32 %0, %1;" : "=f"(t) : "f"(h));
    return h + h * t;
}
__device__ __forceinline__ uint32_t packbf(float lo, float hi) {
    uint32_t r;
    asm("cvt.rn.bf16x2.f32 %0, %1, %2;" : "=r"(r) : "f"(hi), "f"(lo));
    return r;
}
__device__ __forceinline__ float bf16val(float v) {
    return __bfloat162float(__float2bfloat16(v));
}
__device__ __forceinline__ void pack_hl(float x, float y, uint32_t& h, uint32_t& l) {
    h = packbf(x, y);
    l = packbf(x - bf16val(x), y - bf16val(y));
}
__device__ __forceinline__ void mma_bf16r(float c[4], const uint32_t a[4], uint32_t bx, uint32_t by) {
    asm volatile(
        "mma.sync.aligned.m16n8k16.row.col.f32.bf16.bf16.f32 "
        "{%0,%1,%2,%3}, {%4,%5,%6,%7}, {%8,%9}, {%0,%1,%2,%3};"
        : "+f"(c[0]), "+f"(c[1]), "+f"(c[2]), "+f"(c[3])
        : "r"(a[0]), "r"(a[1]), "r"(a[2]), "r"(a[3]), "r"(bx), "r"(by));
}
__device__ __forceinline__ void mma_bf16(float c[4], const uint32_t a[4], uint2 b) {
    mma_bf16r(c, a, b.x, b.y);
}
__device__ __forceinline__ void mma3(float c[4], const uint32_t ah[4],
                                     const uint32_t al[4], uint4 B) {
    mma_bf16r(c, ah, B.x, B.y);
    mma_bf16r(c, al, B.x, B.y);
    mma_bf16r(c, ah, B.z, B.w);
}

// ---------------------------------------------------------------------------
// Edge MLP kernel. Warp = 16-edge strip.
__global__ void __launch_bounds__(256, 2)
edge_mma_kernel(const float* __restrict__ edge_attr,
                const int*   __restrict__ edge_index,
                const float* __restrict__ edge_weight,
                const float* __restrict__ W1, const float* __restrict__ b1,
                const float* __restrict__ W2, const float* __restrict__ b2,
                const float* __restrict__ W3, const float* __restrict__ b3,
                int E)
{
    __shared__ uint4 sB1[8][32];    // {h0,h1,l0,l1}
    __shared__ uint4 sB2[16][32];
    __shared__ uint4 sB3[48][32];
    __shared__ float sb1[32], sb2[64], sb3[96];

    const int tid = threadIdx.x;

    {
        int i = tid;
        int f = i >> 5, l = i & 31;
        int nt = f >> 1, kf = f & 1;
        int n = nt * 8 + (l >> 2), k0 = kf * 16 + ((l & 3) << 1);
        const float* Wr = W1 + n * 32 + k0;
        uint32_t h0, l0, h1, l1;
        pack_hl(Wr[0], Wr[1], h0, l0);
        pack_hl(Wr[8], Wr[9], h1, l1);
        sB1[f][l] = make_uint4(h0, h1, l0, l1);
    }
    for (int i = tid; i < 512; i += 256) {
        int f = i >> 5, l = i & 31;
        int nt = f >> 1, kf = f & 1;
        int n = nt * 8 + (l >> 2), k0 = kf * 16 + ((l & 3) << 1);
        const float* Wr = W2 + n * 32 + k0;
        uint32_t h0, l0, h1, l1;
        pack_hl(Wr[0], Wr[1], h0, l0);
        pack_hl(Wr[8], Wr[9], h1, l1);
        sB2[f][l] = make_uint4(h0, h1, l0, l1);
    }
    for (int i = tid; i < 1536; i += 256) {
        int f = i >> 5, l = i & 31;
        int nt = f >> 2, kf = f & 3;
        int n = nt * 8 + (l >> 2), k0 = kf * 16 + ((l & 3) << 1);
        const float* Wr = W3 + n * 64 + k0;
        uint32_t h0, l0, h1, l1;
        pack_hl(Wr[0], Wr[1], h0, l0);
        pack_hl(Wr[8], Wr[9], h1, l1);
        sB3[f][l] = make_uint4(h0, h1, l0, l1);
    }
    if (tid < 32) sb1[tid] = b1[tid];
    if (tid < 64) sb2[tid] = b2[tid];
    if (tid < 96) sb3[tid] = b3[tid];
    __syncthreads();

    const int wid = tid >> 5, lane = tid & 31;
    const int r1 = lane >> 2;
    const int tig = lane & 3;
    const int q  = tig << 1;
    const int nStrips = (E + 15) >> 4;

    for (int strip = blockIdx.x * 8 + wid; strip < nStrips;
         strip += gridDim.x * 8) {
        int e0 = strip << 4;
        int eA = e0 + r1, eB = eA + 8;
        int eAc = min(eA, E - 1), eBc = min(eB, E - 1);

        uint32_t A1h[2][4], A1l[2][4];
        #pragma unroll
        for (int kf = 0; kf < 2; kf++) {
            const float* pa = edge_attr + (size_t)eAc * 32 + kf * 16 + q;
            const float* pb = edge_attr + (size_t)eBc * 32 + kf * 16 + q;
            float2 v0 = *(const float2*)pa;
            float2 v1 = *(const float2*)pb;
            float2 v2 = *(const float2*)(pa + 8);
            float2 v3 = *(const float2*)(pb + 8);
            pack_hl(v0.x, v0.y, A1h[kf][0], A1l[kf][0]);
            pack_hl(v1.x, v1.y, A1h[kf][1], A1l[kf][1]);
            pack_hl(v2.x, v2.y, A1h[kf][2], A1l[kf][2]);
            pack_hl(v3.x, v3.y, A1h[kf][3], A1l[kf][3]);
        }

        float D1[4][4];
        #pragma unroll
        for (int nt = 0; nt < 4; nt++) {
            float bb0 = sb1[nt * 8 + q], bb1 = sb1[nt * 8 + q + 1];
            D1[nt][0] = bb0; D1[nt][1] = bb1; D1[nt][2] = bb0; D1[nt][3] = bb1;
            #pragma unroll
            for (int kf = 0; kf < 2; kf++)
                mma3(D1[nt], A1h[kf], A1l[kf], sB1[nt * 2 + kf][lane]);
        }

        uint32_t A2h[2][4], A2l[2][4];
        #pragma unroll
        for (int kf = 0; kf < 2; kf++) {
            int na = 2 * kf, nb = 2 * kf + 1;
            float sa0 = silu_f(D1[na][0]), sa1 = silu_f(D1[na][1]);
            float sa2 = silu_f(D1[na][2]), sa3 = silu_f(D1[na][3]);
            float sb0 = silu_f(D1[nb][0]), sb1v = silu_f(D1[nb][1]);
            float sb2v = silu_f(D1[nb][2]), sb3v = silu_f(D1[nb][3]);
            pack_hl(sa0, sa1, A2h[kf][0], A2l[kf][0]);
            pack_hl(sa2, sa3, A2h[kf][1], A2l[kf][1]);
            pack_hl(sb0, sb1v, A2h[kf][2], A2l[kf][2]);
            pack_hl(sb2v, sb3v, A2h[kf][3], A2l[kf][3]);
        }

        float D2[8][4];
        #pragma unroll
        for (int nt = 0; nt < 8; nt++) {
            float bb0 = sb2[nt * 8 + q], bb1 = sb2[nt * 8 + q + 1];
            D2[nt][0] = bb0; D2[nt][1] = bb1; D2[nt][2] = bb0; D2[nt][3] = bb1;
            #pragma unroll
            for (int kf = 0; kf < 2; kf++)
                mma3(D2[nt], A2h[kf], A2l[kf], sB2[nt * 2 + kf][lane]);
        }

        uint32_t A3h[4][4], A3l[4][4];
        #pragma unroll
        for (int kf = 0; kf < 4; kf++) {
            int na = 2 * kf, nb = 2 * kf + 1;
            float sa0 = silu_f(D2[na][0]), sa1 = silu_f(D2[na][1]);
            float sa2 = silu_f(D2[na][2]), sa3 = silu_f(D2[na][3]);
            float sb0 = silu_f(D2[nb][0]), sb1v = silu_f(D2[nb][1]);
            float sb2v = silu_f(D2[nb][2]), sb3v = silu_f(D2[nb][3]);
            pack_hl(sa0, sa1, A3h[kf][0], A3l[kf][0]);
            pack_hl(sa2, sa3, A3h[kf][1], A3l[kf][1]);
            pack_hl(sb0, sb1v, A3h[kf][2], A3l[kf][2]);
            pack_hl(sb2v, sb3v, A3h[kf][3], A3l[kf][3]);
        }

        float D3[12][4];
        #pragma unroll
        for (int nt = 0; nt < 12; nt++) {
            float bb0 = sb3[nt * 8 + q], bb1 = sb3[nt * 8 + q + 1];
            D3[nt][0] = bb0; D3[nt][1] = bb1; D3[nt][2] = bb0; D3[nt][3] = bb1;
            #pragma unroll
            for (int kf = 0; kf < 4; kf++)
                mma3(D3[nt], A3h[kf], A3l[kf], sB3[nt * 4 + kf][lane]);
        }

        // ---- epilogue: silu*Cc, pair lanes -> red.v4 scatter ----
        float wA = edge_weight[eAc], wB = edge_weight[eBc];
        float CcA = (wA < CUTOFF_F)
                  ? 0.5f * (__cosf(wA * (PI_F / CUTOFF_F)) + 1.0f) : 0.0f;
        float CcB = (wB < CUTOFF_F)
                  ? 0.5f * (__cosf(wB * (PI_F / CUTOFF_F)) + 1.0f) : 0.0f;
        int dA = edge_index[E + eAc], dB = edge_index[E + eBc];
        bool okA = eA < E, okB = eB < E;

        int colbase = (tig >> 1) << 2;
        bool isEven = (tig & 1) == 0;
        float* gP = g_acc + (isEven ? (size_t)dA : (size_t)dB) * 96 + colbase;
        bool ok = isEven ? okA : okB;

        #pragma unroll
        for (int nt = 0; nt < 12; nt++) {
            float t0 = silu_f(D3[nt][0]) * CcA;
            float t1 = silu_f(D3[nt][1]) * CcA;
            float t2 = silu_f(D3[nt][2]) * CcB;
            float t3 = silu_f(D3[nt][3]) * CcB;
            float p0 = __shfl_xor_sync(0xFFFFFFFFu, t0, 1);
            float p1 = __shfl_xor_sync(0xFFFFFFFFu, t1, 1);
            float p2 = __shfl_xor_sync(0xFFFFFFFFu, t2, 1);
            float p3 = __shfl_xor_sync(0xFFFFFFFFu, t3, 1);
            float v0 = isEven ? t0 : p2;
            float v1 = isEven ? t1 : p3;
            float v2 = isEven ? p0 : t2;
            float v3 = isEven ? p1 : t3;
            if (ok) {
                asm volatile("red.global.add.v4.f32 [%0], {%1, %2, %3, %4};"
                             :: "l"(gP + nt * 8),
                                "f"(v0), "f"(v1), "f"(v2), "f"(v3) : "memory");
            }
        }
    }
}

// ---------------------------------------------------------------------------
// Node kernel: MMA mixing, in-place cr + separate rt8 result rows.
#define RS 36          // row stride in floats
#define RT8_BASE 144   // rows 144..159 hold rt8 GEMM results

// One m16 row-tile GEMM: A-frags from rows 16*rt.., results to rows wrBase..
__device__ __forceinline__ void gemm_tile(
    float* cr, const uint2* sBh, const uint2* sBl,
    int rt, int mat, int gr, int tig, int lane,
    int nt0, int nt1, int wrBase)
{
    const float* crow0 = cr + (16 * rt + gr) * RS;
    const float* crow1 = crow0 + 8 * RS;
    uint32_t Ah[2][4], Al[2][4];
    #pragma unroll
    for (int kf = 0; kf < 2; kf++) {
        int c0 = kf * 16 + 2 * tig;
        float2 v0 = *(const float2*)(crow0 + c0);
        float2 v1 = *(const float2*)(crow1 + c0);
        float2 v2 = *(const float2*)(crow0 + c0 + 8);
        float2 v3 = *(const float2*)(crow1 + c0 + 8);
        pack_hl(v0.x, v0.y, Ah[kf][0], Al[kf][0]);
        pack_hl(v1.x, v1.y, Ah[kf][1], Al[kf][1]);
        pack_hl(v2.x, v2.y, Ah[kf][2], Al[kf][2]);
        pack_hl(v3.x, v3.y, Ah[kf][3], Al[kf][3]);
    }
    float* wr0 = cr + (wrBase + gr) * RS + 2 * tig;
    float* wr1 = wr0 + 8 * RS;
    #pragma unroll 4
    for (int nt = nt0; nt < nt1; nt++) {
        float D[4] = {0.f, 0.f, 0.f, 0.f};
        #pragma unroll
        for (int kf = 0; kf < 2; kf++) {
            uint2 Bh = sBh[mat * 256 + (nt * 2 + kf) * 32 + lane];
            uint2 Bl = sBl[mat * 256 + (nt * 2 + kf) * 32 + lane];
            mma_bf16(D, Ah[kf], Bh);
            mma_bf16(D, Al[kf], Bh);
            mma_bf16(D, Ah[kf], Bl);
        }
        *(float2*)(wr0 + nt * 8) = make_float2(D[0], D[1]);
        *(float2*)(wr1 + nt * 8) = make_float2(D[2], D[3]);
    }
}

__global__ void __launch_bounds__(256)
node_mma_kernel(const float* __restrict__ X,
                const float* __restrict__ Wt,
                float* __restrict__ out,
                int nNodes, int nStrips)
{
    extern __shared__ char smem[];
    uint2* sBh  = (uint2*)smem;                       // [mat*256 + f*32 + l]
    uint2* sBl  = (uint2*)(smem + 12288);
    float* cr   = (float*)(smem + 24576);             // [160][RS]

    const int tid  = threadIdx.x;
    const int lane = tid & 31, wid = tid >> 5;
    const int gr   = lane >> 2, tig = lane & 3;

    for (int i = tid; i < 1536; i += 256) {
        int mat = i >> 8, rem = i & 255;
        int f = rem >> 5, l = rem & 31;
        int nt = f >> 1, kf = f & 1;
        int n = nt * 8 + (l >> 2), k0 = kf * 16 + ((l & 3) << 1);
        const float* Wr = Wt + mat * 1024 + n * 32 + k0;
        uint32_t h0, l0, h1, l1;
        pack_hl(Wr[0], Wr[1], h0, l0);
        pack_hl(Wr[8], Wr[9], h1, l1);
        sBh[i] = make_uint2(h0, h1);
        sBl[i] = make_uint2(l0, l1);
    }
    __syncthreads();

    const int nl0 = tid >> 5;
    const int u   = lane;
    const int matS1 = (wid == 0) ? 0 : (wid < 4) ? 1 : 2;

    for (int s = blockIdx.x; s < nStrips; s += gridDim.x) {
        const int nodeBase = s << 4;
        float Xn[2][9];

        // ---------- EW-A: normalize + decompose -> cr rows 0..143 ----------
        #pragma unroll
        for (int cc = 0; cc < 2; cc++) {
            int r0 = nl0 + cc * 8;
            int n  = nodeBase + r0;
            int nc = min(n, nNodes - 1);
            float nrm = 1.0f;
            #pragma unroll
            for (int t = 0; t < 9; t++) {
                float v = X[((size_t)nc * 9 + t) * 32 + u];
                Xn[cc][t] = v; nrm += v * v;
            }
            float inv = __fdividef(1.0f, nrm);
            #pragma unroll
            for (int t = 0; t < 9; t++) Xn[cc][t] *= inv;

            const float* x = Xn[cc];
            float tr3 = (x[0] + x[4] + x[8]) * (1.0f / 3.0f);
            float* cp = cr + r0 * RS + u;
            cp[0 * 16 * RS] = tr3;
            cp[1 * 16 * RS] = 0.5f * (x[1] - x[3]);
            cp[2 * 16 * RS] = 0.5f * (x[2] - x[6]);
            cp[3 * 16 * RS] = 0.5f * (x[5] - x[7]);
            cp[4 * 16 * RS] = x[0] - tr3;
            cp[5 * 16 * RS] = 0.5f * (x[1] + x[3]);
            cp[6 * 16 * RS] = 0.5f * (x[2] + x[6]);
            cp[7 * 16 * RS] = x[4] - tr3;
            cp[8 * 16 * RS] = 0.5f * (x[5] + x[7]);
        }
        __syncthreads();

        // ---------- GEMM stage 1 (mats 0..2) ----------
        gemm_tile(cr, sBh, sBl, wid, matS1, gr, tig, lane, 0, 4, 16 * wid);
        if (wid < 4)
            gemm_tile(cr, sBh, sBl, 8, 2, gr, tig, lane, wid, wid + 1, RT8_BASE);
        __syncthreads();

        // ---------- EW-B: msg combine, M = YG+GY, renorm -> cr ----------
        #pragma unroll
        for (int cc = 0; cc < 2; cc++) {
            int r0 = nl0 + cc * 8;
            int n  = nodeBase + r0;
            float* rp = cr + r0 * RS + u;
            float Ip  = rp[0 * 16 * RS];
            float a01 = rp[1 * 16 * RS];
            float a02 = rp[2 * 16 * RS];
            float a12 = rp[3 * 16 * RS];
            float s00 = rp[4 * 16 * RS];
            float s01 = rp[5 * 16 * RS];
            float s02 = rp[6 * 16 * RS];
            float s11 = rp[7 * 16 * RS];
            float s12 = rp[9 * 16 * RS];            // comp8 result at RT8_BASE
            float s22 = -(s00 + s11);

            float sI = 0.f, sA = 0.f, sS = 0.f;
            if (n < nNodes) {
                float* ap = g_acc + (size_t)n * 96 + u * 3;
                sI = ap[0]; sA = ap[1]; sS = ap[2];
                ap[0] = 0.f; ap[1] = 0.f; ap[2] = 0.f;
            }

            float Y[9], G[9];
            Y[0] = Ip + s00;  Y[1] = a01 + s01;  Y[2] = a02 + s02;
            Y[3] = s01 - a01; Y[4] = Ip + s11;   Y[5] = a12 + s12;
            Y[6] = s02 - a02; Y[7] = s12 - a12;  Y[8] = Ip + s22;
            G[0] = Ip*sI + s00*sS;  G[1] = a01*sA + s01*sS;  G[2] = a02*sA + s02*sS;
            G[3] = s01*sS - a01*sA; G[4] = Ip*sI + s11*sS;   G[5] = a12*sA + s12*sS;
            G[6] = s02*sS - a02*sA; G[7] = s12*sS - a12*sA;  G[8] = Ip*sI + s22*sS;

            float M[9];
            #pragma unroll
            for (int i = 0; i < 3; i++)
                #pragma unroll
                for (int l = 0; l < 3; l++) {
                    float a2 = 0.0f;
                    #pragma unroll
                    for (int j = 0; j < 3; j++)
                        a2 += Y[i*3+j] * G[j*3+l] + G[i*3+j] * Y[j*3+l];
                    M[i*3+l] = a2;
                }

            float np = 1.0f;
            #pragma unroll
            for (int t = 0; t < 9; t++) np += M[t] * M[t];
            float inv2 = __fdividef(1.0f, np);
            float trm = (M[0] + M[4] + M[8]) * (1.0f / 3.0f);

            rp[0 * 16 * RS] = trm * inv2;
            rp[1 * 16 * RS] = 0.5f * (M[1] - M[3]) * inv2;
            rp[2 * 16 * RS] = 0.5f * (M[2] - M[6]) * inv2;
            rp[3 * 16 * RS] = 0.5f * (M[5] - M[7]) * inv2;
            rp[4 * 16 * RS] = (M[0] - trm) * inv2;
            rp[5 * 16 * RS] = 0.5f * (M[1] + M[3]) * inv2;
            rp[6 * 16 * RS] = 0.5f * (M[2] + M[6]) * inv2;
            rp[7 * 16 * RS] = (M[4] - trm) * inv2;
            rp[8 * 16 * RS] = 0.5f * (M[5] + M[7]) * inv2;
        }
        __syncthreads();

        // ---------- GEMM stage 2 (mats 3..5) ----------
        gemm_tile(cr, sBh, sBl, wid, matS1 + 3, gr, tig, lane, 0, 4, 16 * wid);
        if (wid < 4)
            gemm_tile(cr, sBh, sBl, 8, 5, gr, tig, lane, wid, wid + 1, RT8_BASE);
        __syncthreads();

        // ---------- EW-C: D, out = Xn + D + D@D ----------
        #pragma unroll
        for (int cc = 0; cc < 2; cc++) {
            int r0 = nl0 + cc * 8;
            int n  = nodeBase + r0;
            const float* rp = cr + r0 * RS + u;
            float Ip2 = rp[0 * 16 * RS];
            float b01 = rp[1 * 16 * RS];
            float b02 = rp[2 * 16 * RS];
            float b12 = rp[3 * 16 * RS];
            float t00 = rp[4 * 16 * RS];
            float t01 = rp[5 * 16 * RS];
            float t02 = rp[6 * 16 * RS];
            float t11 = rp[7 * 16 * RS];
            float t12 = rp[9 * 16 * RS];            // comp8 result at RT8_BASE
            float t22 = -(t00 + t11);

            float D[9];
            D[0] = Ip2 + t00;  D[1] = b01 + t01;  D[2] = b02 + t02;
            D[3] = t01 - b01;  D[4] = Ip2 + t11;  D[5] = b12 + t12;
            D[6] = t02 - b02;  D[7] = t12 - b12;  D[8] = Ip2 + t22;

            if (n < nNodes) {
                #pragma unroll
                for (int i = 0; i < 3; i++)
                    #pragma unroll
                    for (int l = 0; l < 3; l++) {
                        float o = Xn[cc][i*3+l] + D[i*3+l];
                        #pragma unroll
                        for (int j = 0; j < 3; j++)
                            o += D[i*3+j] * D[j*3+l];
                        out[((size_t)n * 9 + (i*3+l)) * 32 + u] = o;
                    }
            }
        }
        __syncthreads();
    }
}

// ---------------------------------------------------------------------------
extern "C" void kernel_launch(void* const* d_in, const int* in_sizes, int n_in,
                              void* d_out, int out_size)
{
    const float* X           = (const float*)d_in[0];
    const int*   edge_index  = (const int*)  d_in[1];
    const float* edge_weight = (const float*)d_in[2];
    const float* edge_attr   = (const float*)d_in[3];
    const float* W1 = (const float*)d_in[4];
    const float* b1 = (const float*)d_in[5];
    const float* W2 = (const float*)d_in[6];
    const float* b2 = (const float*)d_in[7];
    const float* W3 = (const float*)d_in[8];
    const float* b3 = (const float*)d_in[9];
    const float* Wt = (const float*)d_in[10];
    float* out = (float*)d_out;

    int N = in_sizes[0] / 288;   // X is (N,3,3,32)
    if (N > MAXN) N = MAXN;
    int E = in_sizes[2];         // edge_weight is (E,)

    int nStrips = (E + 15) >> 4;
    int grid = (nStrips + 7) / 8;
    if (grid > 296) grid = 296;

    edge_mma_kernel<<<grid, 256>>>(
        edge_attr, edge_index, edge_weight, W1, b1, W2, b2, W3, b3, E);

    int nodeSmem = 24576 + 160 * RS * 4;   // 47616 bytes
    static bool attr_set = false;
    if (!attr_set) {
        cudaFuncSetAttribute(node_mma_kernel,
                             cudaFuncAttributeMaxDynamicSharedMemorySize, nodeSmem);
        attr_set = true;
    }
    int nodeStrips = (N + 15) / 16;
    int nodeGrid = nodeStrips < 592 ? nodeStrips : 592;
    node_mma_kernel<<<nodeGrid, 256, nodeSmem>>>(X, Wt, out, N, nodeStrips);
}

// round 14
// speedup vs baseline: 1.2233x; 1.0307x over previous
#include <cuda_runtime.h>
#include <cuda_bf16.h>
#include <cstdint>

// ---------------------------------------------------------------------------
// TensorNet interaction.
//   msg[n] = (component tensors of n) * (per-node scalar sums of edge MLP),
//   so the graph part is a scatter-add of 96 edge-MLP outputs into acc[n][96].
//
// R14:
//  * pack_hl: extract the rounded bf16 values directly from the packed
//    register (h<<16 / h&0xFFFF0000) instead of CVT round-trips -- 8 -> 5
//    ops per pair, bit-identical numerics. Pack chain is on the edge
//    kernel's serial critical path.
//  * node: trailing __syncthreads removed (EW-C reads and next-strip EW-A
//    writes of cr are same-thread per (row,col); RT8 rows untouched by EW-A).
// ---------------------------------------------------------------------------

#define MAXN 50000
#define PI_F 3.14159265358979323846f
#define CUTOFF_F 5.0f

__device__ float g_acc[(size_t)MAXN * 96];

// fast silu: v*sigmoid(v) = h + h*tanh(h), h = v/2   (1 MUFU)
__device__ __forceinline__ float silu_f(float v) {
    float h = 0.5f * v;
    float t;
    asm("tanh.approx.f32 %0, %1;" : "=f"(t) : "f"(h));
    return h + h * t;
}
__device__ __forceinline__ uint32_t packbf(float lo, float hi) {
    uint32_t r;
    asm("cvt.rn.bf16x2.f32 %0, %1, %2;" : "=r"(r) : "f"(hi), "f"(lo));
    return r;
}
// hi pack + residual(lo) pack; rounded values extracted from packed reg.
__device__ __forceinline__ void pack_hl(float x, float y, uint32_t& h, uint32_t& l) {
    h = packbf(x, y);                                  // {hi=bf16(y), lo=bf16(x)}
    float fx = __uint_as_float(h << 16);               // == float(bf16(x))
    float fy = __uint_as_float(h & 0xFFFF0000u);       // == float(bf16(y))
    l = packbf(x - fx, y - fy);
}
__device__ __forceinline__ void mma_bf16r(float c[4], const uint32_t a[4], uint32_t bx, uint32_t by) {
    asm volatile(
        "mma.sync.aligned.m16n8k16.row.col.f32.bf16.bf16.f32 "
        "{%0,%1,%2,%3}, {%4,%5,%6,%7}, {%8,%9}, {%0,%1,%2,%3};"
        : "+f"(c[0]), "+f"(c[1]), "+f"(c[2]), "+f"(c[3])
        : "r"(a[0]), "r"(a[1]), "r"(a[2]), "r"(a[3]), "r"(bx), "r"(by));
}
__device__ __forceinline__ void mma_bf16(float c[4], const uint32_t a[4], uint2 b) {
    mma_bf16r(c, a, b.x, b.y);
}
__device__ __forceinline__ void mma3(float c[4], const uint32_t ah[4],
                                     const uint32_t al[4], uint4 B) {
    mma_bf16r(c, ah, B.x, B.y);
    mma_bf16r(c, al, B.x, B.y);
    mma_bf16r(c, ah, B.z, B.w);
}

// ---------------------------------------------------------------------------
// Edge MLP kernel. Warp = 16-edge strip.
__global__ void __launch_bounds__(256, 2)
edge_mma_kernel(const float* __restrict__ edge_attr,
                const int*   __restrict__ edge_index,
                const float* __restrict__ edge_weight,
                const float* __restrict__ W1, const float* __restrict__ b1,
                const float* __restrict__ W2, const float* __restrict__ b2,
                const float* __restrict__ W3, const float* __restrict__ b3,
                int E)
{
    __shared__ uint4 sB1[8][32];    // {h0,h1,l0,l1}
    __shared__ uint4 sB2[16][32];
    __shared__ uint4 sB3[48][32];
    __shared__ float sb1[32], sb2[64], sb3[96];

    const int tid = threadIdx.x;

    {
        int i = tid;
        int f = i >> 5, l = i & 31;
        int nt = f >> 1, kf = f & 1;
        int n = nt * 8 + (l >> 2), k0 = kf * 16 + ((l & 3) << 1);
        const float* Wr = W1 + n * 32 + k0;
        uint32_t h0, l0, h1, l1;
        pack_hl(Wr[0], Wr[1], h0, l0);
        pack_hl(Wr[8], Wr[9], h1, l1);
        sB1[f][l] = make_uint4(h0, h1, l0, l1);
    }
    for (int i = tid; i < 512; i += 256) {
        int f = i >> 5, l = i & 31;
        int nt = f >> 1, kf = f & 1;
        int n = nt * 8 + (l >> 2), k0 = kf * 16 + ((l & 3) << 1);
        const float* Wr = W2 + n * 32 + k0;
        uint32_t h0, l0, h1, l1;
        pack_hl(Wr[0], Wr[1], h0, l0);
        pack_hl(Wr[8], Wr[9], h1, l1);
        sB2[f][l] = make_uint4(h0, h1, l0, l1);
    }
    for (int i = tid; i < 1536; i += 256) {
        int f = i >> 5, l = i & 31;
        int nt = f >> 2, kf = f & 3;
        int n = nt * 8 + (l >> 2), k0 = kf * 16 + ((l & 3) << 1);
        const float* Wr = W3 + n * 64 + k0;
        uint32_t h0, l0, h1, l1;
        pack_hl(Wr[0], Wr[1], h0, l0);
        pack_hl(Wr[8], Wr[9], h1, l1);
        sB3[f][l] = make_uint4(h0, h1, l0, l1);
    }
    if (tid < 32) sb1[tid] = b1[tid];
    if (tid < 64) sb2[tid] = b2[tid];
    if (tid < 96) sb3[tid] = b3[tid];
    __syncthreads();

    const int wid = tid >> 5, lane = tid & 31;
    const int r1 = lane >> 2;
    const int tig = lane & 3;
    const int q  = tig << 1;
    const int nStrips = (E + 15) >> 4;

    for (int strip = blockIdx.x * 8 + wid; strip < nStrips;
         strip += gridDim.x * 8) {
        int e0 = strip << 4;
        int eA = e0 + r1, eB = eA + 8;
        int eAc = min(eA, E - 1), eBc = min(eB, E - 1);

        uint32_t A1h[2][4], A1l[2][4];
        #pragma unroll
        for (int kf = 0; kf < 2; kf++) {
            const float* pa = edge_attr + (size_t)eAc * 32 + kf * 16 + q;
            const float* pb = edge_attr + (size_t)eBc * 32 + kf * 16 + q;
            float2 v0 = *(const float2*)pa;
            float2 v1 = *(const float2*)pb;
            float2 v2 = *(const float2*)(pa + 8);
            float2 v3 = *(const float2*)(pb + 8);
            pack_hl(v0.x, v0.y, A1h[kf][0], A1l[kf][0]);
            pack_hl(v1.x, v1.y, A1h[kf][1], A1l[kf][1]);
            pack_hl(v2.x, v2.y, A1h[kf][2], A1l[kf][2]);
            pack_hl(v3.x, v3.y, A1h[kf][3], A1l[kf][3]);
        }

        float D1[4][4];
        #pragma unroll
        for (int nt = 0; nt < 4; nt++) {
            float bb0 = sb1[nt * 8 + q], bb1 = sb1[nt * 8 + q + 1];
            D1[nt][0] = bb0; D1[nt][1] = bb1; D1[nt][2] = bb0; D1[nt][3] = bb1;
            #pragma unroll
            for (int kf = 0; kf < 2; kf++)
                mma3(D1[nt], A1h[kf], A1l[kf], sB1[nt * 2 + kf][lane]);
        }

        uint32_t A2h[2][4], A2l[2][4];
        #pragma unroll
        for (int kf = 0; kf < 2; kf++) {
            int na = 2 * kf, nb = 2 * kf + 1;
            float sa0 = silu_f(D1[na][0]), sa1 = silu_f(D1[na][1]);
            float sa2 = silu_f(D1[na][2]), sa3 = silu_f(D1[na][3]);
            float sb0 = silu_f(D1[nb][0]), sb1v = silu_f(D1[nb][1]);
            float sb2v = silu_f(D1[nb][2]), sb3v = silu_f(D1[nb][3]);
            pack_hl(sa0, sa1, A2h[kf][0], A2l[kf][0]);
            pack_hl(sa2, sa3, A2h[kf][1], A2l[kf][1]);
            pack_hl(sb0, sb1v, A2h[kf][2], A2l[kf][2]);
            pack_hl(sb2v, sb3v, A2h[kf][3], A2l[kf][3]);
        }

        float D2[8][4];
        #pragma unroll
        for (int nt = 0; nt < 8; nt++) {
            float bb0 = sb2[nt * 8 + q], bb1 = sb2[nt * 8 + q + 1];
            D2[nt][0] = bb0; D2[nt][1] = bb1; D2[nt][2] = bb0; D2[nt][3] = bb1;
            #pragma unroll
            for (int kf = 0; kf < 2; kf++)
                mma3(D2[nt], A2h[kf], A2l[kf], sB2[nt * 2 + kf][lane]);
        }

        uint32_t A3h[4][4], A3l[4][4];
        #pragma unroll
        for (int kf = 0; kf < 4; kf++) {
            int na = 2 * kf, nb = 2 * kf + 1;
            float sa0 = silu_f(D2[na][0]), sa1 = silu_f(D2[na][1]);
            float sa2 = silu_f(D2[na][2]), sa3 = silu_f(D2[na][3]);
            float sb0 = silu_f(D2[nb][0]), sb1v = silu_f(D2[nb][1]);
            float sb2v = silu_f(D2[nb][2]), sb3v = silu_f(D2[nb][3]);
            pack_hl(sa0, sa1, A3h[kf][0], A3l[kf][0]);
            pack_hl(sa2, sa3, A3h[kf][1], A3l[kf][1]);
            pack_hl(sb0, sb1v, A3h[kf][2], A3l[kf][2]);
            pack_hl(sb2v, sb3v, A3h[kf][3], A3l[kf][3]);
        }

        float D3[12][4];
        #pragma unroll
        for (int nt = 0; nt < 12; nt++) {
            float bb0 = sb3[nt * 8 + q], bb1 = sb3[nt * 8 + q + 1];
            D3[nt][0] = bb0; D3[nt][1] = bb1; D3[nt][2] = bb0; D3[nt][3] = bb1;
            #pragma unroll
            for (int kf = 0; kf < 4; kf++)
                mma3(D3[nt], A3h[kf], A3l[kf], sB3[nt * 4 + kf][lane]);
        }

        // ---- epilogue: silu*Cc, pair lanes -> red.v4 scatter ----
        float wA = edge_weight[eAc], wB = edge_weight[eBc];
        float CcA = (wA < CUTOFF_F)
                  ? 0.5f * (__cosf(wA * (PI_F / CUTOFF_F)) + 1.0f) : 0.0f;
        float CcB = (wB < CUTOFF_F)
                  ? 0.5f * (__cosf(wB * (PI_F / CUTOFF_F)) + 1.0f) : 0.0f;
        int dA = edge_index[E + eAc], dB = edge_index[E + eBc];
        bool okA = eA < E, okB = eB < E;

        int colbase = (tig >> 1) << 2;
        bool isEven = (tig & 1) == 0;
        float* gP = g_acc + (isEven ? (size_t)dA : (size_t)dB) * 96 + colbase;
        bool ok = isEven ? okA : okB;

        #pragma unroll
        for (int nt = 0; nt < 12; nt++) {
            float t0 = silu_f(D3[nt][0]) * CcA;
            float t1 = silu_f(D3[nt][1]) * CcA;
            float t2 = silu_f(D3[nt][2]) * CcB;
            float t3 = silu_f(D3[nt][3]) * CcB;
            float p0 = __shfl_xor_sync(0xFFFFFFFFu, t0, 1);
            float p1 = __shfl_xor_sync(0xFFFFFFFFu, t1, 1);
            float p2 = __shfl_xor_sync(0xFFFFFFFFu, t2, 1);
            float p3 = __shfl_xor_sync(0xFFFFFFFFu, t3, 1);
            float v0 = isEven ? t0 : p2;
            float v1 = isEven ? t1 : p3;
            float v2 = isEven ? p0 : t2;
            float v3 = isEven ? p1 : t3;
            if (ok) {
                asm volatile("red.global.add.v4.f32 [%0], {%1, %2, %3, %4};"
                             :: "l"(gP + nt * 8),
                                "f"(v0), "f"(v1), "f"(v2), "f"(v3) : "memory");
            }
        }
    }
}

// ---------------------------------------------------------------------------
// Node kernel: MMA mixing, in-place cr + separate rt8 result rows.
#define RS 36          // row stride in floats
#define RT8_BASE 144   // rows 144..159 hold rt8 GEMM results

__device__ __forceinline__ void gemm_tile(
    float* cr, const uint2* sBh, const uint2* sBl,
    int rt, int mat, int gr, int tig, int lane,
    int nt0, int nt1, int wrBase)
{
    const float* crow0 = cr + (16 * rt + gr) * RS;
    const float* crow1 = crow0 + 8 * RS;
    uint32_t Ah[2][4], Al[2][4];
    #pragma unroll
    for (int kf = 0; kf < 2; kf++) {
        int c0 = kf * 16 + 2 * tig;
        float2 v0 = *(const float2*)(crow0 + c0);
        float2 v1 = *(const float2*)(crow1 + c0);
        float2 v2 = *(const float2*)(crow0 + c0 + 8);
        float2 v3 = *(const float2*)(crow1 + c0 + 8);
        pack_hl(v0.x, v0.y, Ah[kf][0], Al[kf][0]);
        pack_hl(v1.x, v1.y, Ah[kf][1], Al[kf][1]);
        pack_hl(v2.x, v2.y, Ah[kf][2], Al[kf][2]);
        pack_hl(v3.x, v3.y, Ah[kf][3], Al[kf][3]);
    }
    float* wr0 = cr + (wrBase + gr) * RS + 2 * tig;
    float* wr1 = wr0 + 8 * RS;
    #pragma unroll 4
    for (int nt = nt0; nt < nt1; nt++) {
        float D[4] = {0.f, 0.f, 0.f, 0.f};
        #pragma unroll
        for (int kf = 0; kf < 2; kf++) {
            uint2 Bh = sBh[mat * 256 + (nt * 2 + kf) * 32 + lane];
            uint2 Bl = sBl[mat * 256 + (nt * 2 + kf) * 32 + lane];
            mma_bf16(D, Ah[kf], Bh);
            mma_bf16(D, Al[kf], Bh);
            mma_bf16(D, Ah[kf], Bl);
        }
        *(float2*)(wr0 + nt * 8) = make_float2(D[0], D[1]);
        *(float2*)(wr1 + nt * 8) = make_float2(D[2], D[3]);
    }
}

__global__ void __launch_bounds__(256)
node_mma_kernel(const float* __restrict__ X,
                const float* __restrict__ Wt,
                float* __restrict__ out,
                int nNodes, int nStrips)
{
    extern __shared__ char smem[];
    uint2* sBh  = (uint2*)smem;                       // [mat*256 + f*32 + l]
    uint2* sBl  = (uint2*)(smem + 12288);
    float* cr   = (float*)(smem + 24576);             // [160][RS]

    const int tid  = threadIdx.x;
    const int lane = tid & 31, wid = tid >> 5;
    const int gr   = lane >> 2, tig = lane & 3;

    for (int i = tid; i < 1536; i += 256) {
        int mat = i >> 8, rem = i & 255;
        int f = rem >> 5, l = rem & 31;
        int nt = f >> 1, kf = f & 1;
        int n = nt * 8 + (l >> 2), k0 = kf * 16 + ((l & 3) << 1);
        const float* Wr = Wt + mat * 1024 + n * 32 + k0;
        uint32_t h0, l0, h1, l1;
        pack_hl(Wr[0], Wr[1], h0, l0);
        pack_hl(Wr[8], Wr[9], h1, l1);
        sBh[i] = make_uint2(h0, h1);
        sBl[i] = make_uint2(l0, l1);
    }
    __syncthreads();

    const int nl0 = tid >> 5;
    const int u   = lane;
    const int matS1 = (wid == 0) ? 0 : (wid < 4) ? 1 : 2;

    for (int s = blockIdx.x; s < nStrips; s += gridDim.x) {
        const int nodeBase = s << 4;
        float Xn[2][9];

        // ---------- EW-A: normalize + decompose -> cr rows 0..143 ----------
        // (No barrier needed after previous strip's EW-C: each (row,col) cell
        //  written here was read in EW-C by the SAME thread, and EW-A never
        //  touches the RT8 rows.)
        #pragma unroll
        for (int cc = 0; cc < 2; cc++) {
            int r0 = nl0 + cc * 8;
            int n  = nodeBase + r0;
            int nc = min(n, nNodes - 1);
            float nrm = 1.0f;
            #pragma unroll
            for (int t = 0; t < 9; t++) {
                float v = X[((size_t)nc * 9 + t) * 32 + u];
                Xn[cc][t] = v; nrm += v * v;
            }
            float inv = __fdividef(1.0f, nrm);
            #pragma unroll
            for (int t = 0; t < 9; t++) Xn[cc][t] *= inv;

            const float* x = Xn[cc];
            float tr3 = (x[0] + x[4] + x[8]) * (1.0f / 3.0f);
            float* cp = cr + r0 * RS + u;
            cp[0 * 16 * RS] = tr3;
            cp[1 * 16 * RS] = 0.5f * (x[1] - x[3]);
            cp[2 * 16 * RS] = 0.5f * (x[2] - x[6]);
            cp[3 * 16 * RS] = 0.5f * (x[5] - x[7]);
            cp[4 * 16 * RS] = x[0] - tr3;
            cp[5 * 16 * RS] = 0.5f * (x[1] + x[3]);
            cp[6 * 16 * RS] = 0.5f * (x[2] + x[6]);
            cp[7 * 16 * RS] = x[4] - tr3;
            cp[8 * 16 * RS] = 0.5f * (x[5] + x[7]);
        }
        __syncthreads();

        // ---------- GEMM stage 1 (mats 0..2) ----------
        gemm_tile(cr, sBh, sBl, wid, matS1, gr, tig, lane, 0, 4, 16 * wid);
        if (wid < 4)
            gemm_tile(cr, sBh, sBl, 8, 2, gr, tig, lane, wid, wid + 1, RT8_BASE);
        __syncthreads();

        // ---------- EW-B: msg combine, M = YG+GY, renorm -> cr ----------
        #pragma unroll
        for (int cc = 0; cc < 2; cc++) {
            int r0 = nl0 + cc * 8;
            int n  = nodeBase + r0;
            float* rp = cr + r0 * RS + u;
            float Ip  = rp[0 * 16 * RS];
            float a01 = rp[1 * 16 * RS];
            float a02 = rp[2 * 16 * RS];
            float a12 = rp[3 * 16 * RS];
            float s00 = rp[4 * 16 * RS];
            float s01 = rp[5 * 16 * RS];
            float s02 = rp[6 * 16 * RS];
            float s11 = rp[7 * 16 * RS];
            float s12 = rp[9 * 16 * RS];            // comp8 result at RT8_BASE
            float s22 = -(s00 + s11);

            float sI = 0.f, sA = 0.f, sS = 0.f;
            if (n < nNodes) {
                float* ap = g_acc + (size_t)n * 96 + u * 3;
                sI = ap[0]; sA = ap[1]; sS = ap[2];
                ap[0] = 0.f; ap[1] = 0.f; ap[2] = 0.f;
            }

            float Y[9], G[9];
            Y[0] = Ip + s00;  Y[1] = a01 + s01;  Y[2] = a02 + s02;
            Y[3] = s01 - a01; Y[4] = Ip + s11;   Y[5] = a12 + s12;
            Y[6] = s02 - a02; Y[7] = s12 - a12;  Y[8] = Ip + s22;
            G[0] = Ip*sI + s00*sS;  G[1] = a01*sA + s01*sS;  G[2] = a02*sA + s02*sS;
            G[3] = s01*sS - a01*sA; G[4] = Ip*sI + s11*sS;   G[5] = a12*sA + s12*sS;
            G[6] = s02*sS - a02*sA; G[7] = s12*sS - a12*sA;  G[8] = Ip*sI + s22*sS;

            float M[9];
            #pragma unroll
            for (int i = 0; i < 3; i++)
                #pragma unroll
                for (int l = 0; l < 3; l++) {
                    float a2 = 0.0f;
                    #pragma unroll
                    for (int j = 0; j < 3; j++)
                        a2 += Y[i*3+j] * G[j*3+l] + G[i*3+j] * Y[j*3+l];
                    M[i*3+l] = a2;
                }

            float np = 1.0f;
            #pragma unroll
            for (int t = 0; t < 9; t++) np += M[t] * M[t];
            float inv2 = __fdividef(1.0f, np);
            float trm = (M[0] + M[4] + M[8]) * (1.0f / 3.0f);

            rp[0 * 16 * RS] = trm * inv2;
            rp[1 * 16 * RS] = 0.5f * (M[1] - M[3]) * inv2;
            rp[2 * 16 * RS] = 0.5f * (M[2] - M[6]) * inv2;
            rp[3 * 16 * RS] = 0.5f * (M[5] - M[7]) * inv2;
            rp[4 * 16 * RS] = (M[0] - trm) * inv2;
            rp[5 * 16 * RS] = 0.5f * (M[1] + M[3]) * inv2;
            rp[6 * 16 * RS] = 0.5f * (M[2] + M[6]) * inv2;
            rp[7 * 16 * RS] = (M[4] - trm) * inv2;
            rp[8 * 16 * RS] = 0.5f * (M[5] + M[7]) * inv2;
        }
        __syncthreads();

        // ---------- GEMM stage 2 (mats 3..5) ----------
        gemm_tile(cr, sBh, sBl, wid, matS1 + 3, gr, tig, lane, 0, 4, 16 * wid);
        if (wid < 4)
            gemm_tile(cr, sBh, sBl, 8, 5, gr, tig, lane, wid, wid + 1, RT8_BASE);
        __syncthreads();

        // ---------- EW-C: D, out = Xn + D + D@D ----------
        #pragma unroll
        for (int cc = 0; cc < 2; cc++) {
            int r0 = nl0 + cc * 8;
            int n  = nodeBase + r0;
            const float* rp = cr + r0 * RS + u;
            float Ip2 = rp[0 * 16 * RS];
            float b01 = rp[1 * 16 * RS];
            float b02 = rp[2 * 16 * RS];
            float b12 = rp[3 * 16 * RS];
            float t00 = rp[4 * 16 * RS];
            float t01 = rp[5 * 16 * RS];
            float t02 = rp[6 * 16 * RS];
            float t11 = rp[7 * 16 * RS];
            float t12 = rp[9 * 16 * RS];            // comp8 result at RT8_BASE
            float t22 = -(t00 + t11);

            float D[9];
            D[0] = Ip2 + t00;  D[1] = b01 + t01;  D[2] = b02 + t02;
            D[3] = t01 - b01;  D[4] = Ip2 + t11;  D[5] = b12 + t12;
            D[6] = t02 - b02;  D[7] = t12 - b12;  D[8] = Ip2 + t22;

            if (n < nNodes) {
                #pragma unroll
                for (int i = 0; i < 3; i++)
                    #pragma unroll
                    for (int l = 0; l < 3; l++) {
                        float o = Xn[cc][i*3+l] + D[i*3+l];
                        #pragma unroll
                        for (int j = 0; j < 3; j++)
                            o += D[i*3+j] * D[j*3+l];
                        out[((size_t)n * 9 + (i*3+l)) * 32 + u] = o;
                    }
            }
        }
        // no trailing sync: next-strip EW-A writes are same-thread per cell
    }
}

// ---------------------------------------------------------------------------
extern "C" void kernel_launch(void* const* d_in, const int* in_sizes, int n_in,
                              void* d_out, int out_size)
{
    const float* X           = (const float*)d_in[0];
    const int*   edge_index  = (const int*)  d_in[1];
    const float* edge_weight = (const float*)d_in[2];
    const float* edge_attr   = (const float*)d_in[3];
    const float* W1 = (const float*)d_in[4];
    const float* b1 = (const float*)d_in[5];
    const float* W2 = (const float*)d_in[6];
    const float* b2 = (const float*)d_in[7];
    const float* W3 = (const float*)d_in[8];
    const float* b3 = (const float*)d_in[9];
    const float* Wt = (const float*)d_in[10];
    float* out = (float*)d_out;

    int N = in_sizes[0] / 288;   // X is (N,3,3,32)
    if (N > MAXN) N = MAXN;
    int E = in_sizes[2];         // edge_weight is (E,)

    int nStrips = (E + 15) >> 4;
    int grid = (nStrips + 7) / 8;
    if (grid > 296) grid = 296;

    edge_mma_kernel<<<grid, 256>>>(
        edge_attr, edge_index, edge_weight, W1, b1, W2, b2, W3, b3, E);

    int nodeSmem = 24576 + 160 * RS * 4;   // 47616 bytes
    static bool attr_set = false;
    if (!attr_set) {
        cudaFuncSetAttribute(node_mma_kernel,
                             cudaFuncAttributeMaxDynamicSharedMemorySize, nodeSmem);
        attr_set = true;
    }
    int nodeStrips = (N + 15) / 16;
    int nodeGrid = nodeStrips < 592 ? nodeStrips : 592;
    node_mma_kernel<<<nodeGrid, 256, nodeSmem>>>(X, Wt, out, N, nodeStrips);
}

// round 15
// speedup vs baseline: 1.3517x; 1.1050x over previous
#include <cuda_runtime.h>
#include <cuda_bf16.h>
#include <cuda_fp16.h>
#include <cstdint>

// ---------------------------------------------------------------------------
// TensorNet interaction.
//   msg[n] = (component tensors of n) * (per-node scalar sums of edge MLP),
//   so the graph part is a scatter-add of 96 edge-MLP outputs into acc[n][96].
//
// R15: edge MLP moves to f16 with a 2-term split (xh*w + xl*w, w single f16).
//   HMMA count/strip 216 -> 144 (edge is HMMA-throughput-bound), B-frag smem
//   and LDS halve. Per-layer error ~2.8e-4, expected final rel_err ~1e-4
//   (budget 1e-3). Node kernel unchanged (R14: bf16x3, balanced tiles,
//   in-place cr, no trailing sync).
// ---------------------------------------------------------------------------

#define MAXN 50000
#define PI_F 3.14159265358979323846f
#define CUTOFF_F 5.0f

__device__ float g_acc[(size_t)MAXN * 96];

// fast silu: v*sigmoid(v) = h + h*tanh(h), h = v/2   (1 MUFU)
__device__ __forceinline__ float silu_f(float v) {
    float h = 0.5f * v;
    float t;
    asm("tanh.approx.f32 %0, %1;" : "=f"(t) : "f"(h));
    return h + h * t;
}

// ---- bf16 helpers (node kernel) ----
__device__ __forceinline__ uint32_t packbf(float lo, float hi) {
    uint32_t r;
    asm("cvt.rn.bf16x2.f32 %0, %1, %2;" : "=r"(r) : "f"(hi), "f"(lo));
    return r;
}
__device__ __forceinline__ void pack_hl(float x, float y, uint32_t& h, uint32_t& l) {
    h = packbf(x, y);
    float fx = __uint_as_float(h << 16);
    float fy = __uint_as_float(h & 0xFFFF0000u);
    l = packbf(x - fx, y - fy);
}
__device__ __forceinline__ void mma_bf16r(float c[4], const uint32_t a[4], uint32_t bx, uint32_t by) {
    asm volatile(
        "mma.sync.aligned.m16n8k16.row.col.f32.bf16.bf16.f32 "
        "{%0,%1,%2,%3}, {%4,%5,%6,%7}, {%8,%9}, {%0,%1,%2,%3};"
        : "+f"(c[0]), "+f"(c[1]), "+f"(c[2]), "+f"(c[3])
        : "r"(a[0]), "r"(a[1]), "r"(a[2]), "r"(a[3]), "r"(bx), "r"(by));
}
__device__ __forceinline__ void mma_bf16(float c[4], const uint32_t a[4], uint2 b) {
    mma_bf16r(c, a, b.x, b.y);
}

// ---- f16 helpers (edge kernel) ----
__device__ __forceinline__ uint32_t packf16(float lo, float hi) {
    uint32_t r;
    asm("cvt.rn.f16x2.f32 %0, %1, %2;" : "=r"(r) : "f"(hi), "f"(lo));
    return r;
}
// x = hi(f16) + lo(f16 residual)
__device__ __forceinline__ void pack_hl16(float x, float y, uint32_t& h, uint32_t& l) {
    h = packf16(x, y);
    __half2 hh = *reinterpret_cast<__half2*>(&h);
    float fx = __low2float(hh);
    float fy = __high2float(hh);
    l = packf16(x - fx, y - fy);
}
__device__ __forceinline__ void mma_f16r(float c[4], const uint32_t a[4], uint32_t bx, uint32_t by) {
    asm volatile(
        "mma.sync.aligned.m16n8k16.row.col.f32.f16.f16.f32 "
        "{%0,%1,%2,%3}, {%4,%5,%6,%7}, {%8,%9}, {%0,%1,%2,%3};"
        : "+f"(c[0]), "+f"(c[1]), "+f"(c[2]), "+f"(c[3])
        : "r"(a[0]), "r"(a[1]), "r"(a[2]), "r"(a[3]), "r"(bx), "r"(by));
}
// 2-term split against single-precision-f16 B fragment
__device__ __forceinline__ void mma2(float c[4], const uint32_t ah[4],
                                     const uint32_t al[4], uint2 B) {
    mma_f16r(c, ah, B.x, B.y);
    mma_f16r(c, al, B.x, B.y);
}

// ---------------------------------------------------------------------------
// Edge MLP kernel. Warp = 16-edge strip. f16 2-term split.
__global__ void __launch_bounds__(256, 2)
edge_mma_kernel(const float* __restrict__ edge_attr,
                const int*   __restrict__ edge_index,
                const float* __restrict__ edge_weight,
                const float* __restrict__ W1, const float* __restrict__ b1,
                const float* __restrict__ W2, const float* __restrict__ b2,
                const float* __restrict__ W3, const float* __restrict__ b3,
                int E)
{
    __shared__ uint2 sB1[8][32];    // {b0,b1} f16x2 pairs, single precision level
    __shared__ uint2 sB2[16][32];
    __shared__ uint2 sB3[48][32];
    __shared__ float sb1[32], sb2[64], sb3[96];

    const int tid = threadIdx.x;

    {
        int i = tid;
        int f = i >> 5, l = i & 31;
        int nt = f >> 1, kf = f & 1;
        int n = nt * 8 + (l >> 2), k0 = kf * 16 + ((l & 3) << 1);
        const float* Wr = W1 + n * 32 + k0;
        sB1[f][l] = make_uint2(packf16(Wr[0], Wr[1]), packf16(Wr[8], Wr[9]));
    }
    for (int i = tid; i < 512; i += 256) {
        int f = i >> 5, l = i & 31;
        int nt = f >> 1, kf = f & 1;
        int n = nt * 8 + (l >> 2), k0 = kf * 16 + ((l & 3) << 1);
        const float* Wr = W2 + n * 32 + k0;
        sB2[f][l] = make_uint2(packf16(Wr[0], Wr[1]), packf16(Wr[8], Wr[9]));
    }
    for (int i = tid; i < 1536; i += 256) {
        int f = i >> 5, l = i & 31;
        int nt = f >> 2, kf = f & 3;
        int n = nt * 8 + (l >> 2), k0 = kf * 16 + ((l & 3) << 1);
        const float* Wr = W3 + n * 64 + k0;
        sB3[f][l] = make_uint2(packf16(Wr[0], Wr[1]), packf16(Wr[8], Wr[9]));
    }
    if (tid < 32) sb1[tid] = b1[tid];
    if (tid < 64) sb2[tid] = b2[tid];
    if (tid < 96) sb3[tid] = b3[tid];
    __syncthreads();

    const int wid = tid >> 5, lane = tid & 31;
    const int r1 = lane >> 2;
    const int tig = lane & 3;
    const int q  = tig << 1;
    const int nStrips = (E + 15) >> 4;

    for (int strip = blockIdx.x * 8 + wid; strip < nStrips;
         strip += gridDim.x * 8) {
        int e0 = strip << 4;
        int eA = e0 + r1, eB = eA + 8;
        int eAc = min(eA, E - 1), eBc = min(eB, E - 1);

        uint32_t A1h[2][4], A1l[2][4];
        #pragma unroll
        for (int kf = 0; kf < 2; kf++) {
            const float* pa = edge_attr + (size_t)eAc * 32 + kf * 16 + q;
            const float* pb = edge_attr + (size_t)eBc * 32 + kf * 16 + q;
            float2 v0 = *(const float2*)pa;
            float2 v1 = *(const float2*)pb;
            float2 v2 = *(const float2*)(pa + 8);
            float2 v3 = *(const float2*)(pb + 8);
            pack_hl16(v0.x, v0.y, A1h[kf][0], A1l[kf][0]);
            pack_hl16(v1.x, v1.y, A1h[kf][1], A1l[kf][1]);
            pack_hl16(v2.x, v2.y, A1h[kf][2], A1l[kf][2]);
            pack_hl16(v3.x, v3.y, A1h[kf][3], A1l[kf][3]);
        }

        float D1[4][4];
        #pragma unroll
        for (int nt = 0; nt < 4; nt++) {
            float bb0 = sb1[nt * 8 + q], bb1 = sb1[nt * 8 + q + 1];
            D1[nt][0] = bb0; D1[nt][1] = bb1; D1[nt][2] = bb0; D1[nt][3] = bb1;
            #pragma unroll
            for (int kf = 0; kf < 2; kf++)
                mma2(D1[nt], A1h[kf], A1l[kf], sB1[nt * 2 + kf][lane]);
        }

        uint32_t A2h[2][4], A2l[2][4];
        #pragma unroll
        for (int kf = 0; kf < 2; kf++) {
            int na = 2 * kf, nb = 2 * kf + 1;
            float sa0 = silu_f(D1[na][0]), sa1 = silu_f(D1[na][1]);
            float sa2 = silu_f(D1[na][2]), sa3 = silu_f(D1[na][3]);
            float sb0 = silu_f(D1[nb][0]), sb1v = silu_f(D1[nb][1]);
            float sb2v = silu_f(D1[nb][2]), sb3v = silu_f(D1[nb][3]);
            pack_hl16(sa0, sa1, A2h[kf][0], A2l[kf][0]);
            pack_hl16(sa2, sa3, A2h[kf][1], A2l[kf][1]);
            pack_hl16(sb0, sb1v, A2h[kf][2], A2l[kf][2]);
            pack_hl16(sb2v, sb3v, A2h[kf][3], A2l[kf][3]);
        }

        float D2[8][4];
        #pragma unroll
        for (int nt = 0; nt < 8; nt++) {
            float bb0 = sb2[nt * 8 + q], bb1 = sb2[nt * 8 + q + 1];
            D2[nt][0] = bb0; D2[nt][1] = bb1; D2[nt][2] = bb0; D2[nt][3] = bb1;
            #pragma unroll
            for (int kf = 0; kf < 2; kf++)
                mma2(D2[nt], A2h[kf], A2l[kf], sB2[nt * 2 + kf][lane]);
        }

        uint32_t A3h[4][4], A3l[4][4];
        #pragma unroll
        for (int kf = 0; kf < 4; kf++) {
            int na = 2 * kf, nb = 2 * kf + 1;
            float sa0 = silu_f(D2[na][0]), sa1 = silu_f(D2[na][1]);
            float sa2 = silu_f(D2[na][2]), sa3 = silu_f(D2[na][3]);
            float sb0 = silu_f(D2[nb][0]), sb1v = silu_f(D2[nb][1]);
            float sb2v = silu_f(D2[nb][2]), sb3v = silu_f(D2[nb][3]);
            pack_hl16(sa0, sa1, A3h[kf][0], A3l[kf][0]);
            pack_hl16(sa2, sa3, A3h[kf][1], A3l[kf][1]);
            pack_hl16(sb0, sb1v, A3h[kf][2], A3l[kf][2]);
            pack_hl16(sb2v, sb3v, A3h[kf][3], A3l[kf][3]);
        }

        float D3[12][4];
        #pragma unroll
        for (int nt = 0; nt < 12; nt++) {
            float bb0 = sb3[nt * 8 + q], bb1 = sb3[nt * 8 + q + 1];
            D3[nt][0] = bb0; D3[nt][1] = bb1; D3[nt][2] = bb0; D3[nt][3] = bb1;
            #pragma unroll
            for (int kf = 0; kf < 4; kf++)
                mma2(D3[nt], A3h[kf], A3l[kf], sB3[nt * 4 + kf][lane]);
        }

        // ---- epilogue: silu*Cc, pair lanes -> red.v4 scatter ----
        float wA = edge_weight[eAc], wB = edge_weight[eBc];
        float CcA = (wA < CUTOFF_F)
                  ? 0.5f * (__cosf(wA * (PI_F / CUTOFF_F)) + 1.0f) : 0.0f;
        float CcB = (wB < CUTOFF_F)
                  ? 0.5f * (__cosf(wB * (PI_F / CUTOFF_F)) + 1.0f) : 0.0f;
        int dA = edge_index[E + eAc], dB = edge_index[E + eBc];
        bool okA = eA < E, okB = eB < E;

        int colbase = (tig >> 1) << 2;
        bool isEven = (tig & 1) == 0;
        float* gP = g_acc + (isEven ? (size_t)dA : (size_t)dB) * 96 + colbase;
        bool ok = isEven ? okA : okB;

        #pragma unroll
        for (int nt = 0; nt < 12; nt++) {
            float t0 = silu_f(D3[nt][0]) * CcA;
            float t1 = silu_f(D3[nt][1]) * CcA;
            float t2 = silu_f(D3[nt][2]) * CcB;
            float t3 = silu_f(D3[nt][3]) * CcB;
            float p0 = __shfl_xor_sync(0xFFFFFFFFu, t0, 1);
            float p1 = __shfl_xor_sync(0xFFFFFFFFu, t1, 1);
            float p2 = __shfl_xor_sync(0xFFFFFFFFu, t2, 1);
            float p3 = __shfl_xor_sync(0xFFFFFFFFu, t3, 1);
            float v0 = isEven ? t0 : p2;
            float v1 = isEven ? t1 : p3;
            float v2 = isEven ? p0 : t2;
            float v3 = isEven ? p1 : t3;
            if (ok) {
                asm volatile("red.global.add.v4.f32 [%0], {%1, %2, %3, %4};"
                             :: "l"(gP + nt * 8),
                                "f"(v0), "f"(v1), "f"(v2), "f"(v3) : "memory");
            }
        }
    }
}

// ---------------------------------------------------------------------------
// Node kernel (R14, unchanged): bf16x3 MMA mixing, in-place cr + RT8 rows.
#define RS 36
#define RT8_BASE 144

__device__ __forceinline__ void gemm_tile(
    float* cr, const uint2* sBh, const uint2* sBl,
    int rt, int mat, int gr, int tig, int lane,
    int nt0, int nt1, int wrBase)
{
    const float* crow0 = cr + (16 * rt + gr) * RS;
    const float* crow1 = crow0 + 8 * RS;
    uint32_t Ah[2][4], Al[2][4];
    #pragma unroll
    for (int kf = 0; kf < 2; kf++) {
        int c0 = kf * 16 + 2 * tig;
        float2 v0 = *(const float2*)(crow0 + c0);
        float2 v1 = *(const float2*)(crow1 + c0);
        float2 v2 = *(const float2*)(crow0 + c0 + 8);
        float2 v3 = *(const float2*)(crow1 + c0 + 8);
        pack_hl(v0.x, v0.y, Ah[kf][0], Al[kf][0]);
        pack_hl(v1.x, v1.y, Ah[kf][1], Al[kf][1]);
        pack_hl(v2.x, v2.y, Ah[kf][2], Al[kf][2]);
        pack_hl(v3.x, v3.y, Ah[kf][3], Al[kf][3]);
    }
    float* wr0 = cr + (wrBase + gr) * RS + 2 * tig;
    float* wr1 = wr0 + 8 * RS;
    #pragma unroll 4
    for (int nt = nt0; nt < nt1; nt++) {
        float D[4] = {0.f, 0.f, 0.f, 0.f};
        #pragma unroll
        for (int kf = 0; kf < 2; kf++) {
            uint2 Bh = sBh[mat * 256 + (nt * 2 + kf) * 32 + lane];
            uint2 Bl = sBl[mat * 256 + (nt * 2 + kf) * 32 + lane];
            mma_bf16(D, Ah[kf], Bh);
            mma_bf16(D, Al[kf], Bh);
            mma_bf16(D, Ah[kf], Bl);
        }
        *(float2*)(wr0 + nt * 8) = make_float2(D[0], D[1]);
        *(float2*)(wr1 + nt * 8) = make_float2(D[2], D[3]);
    }
}

__global__ void __launch_bounds__(256)
node_mma_kernel(const float* __restrict__ X,
                const float* __restrict__ Wt,
                float* __restrict__ out,
                int nNodes, int nStrips)
{
    extern __shared__ char smem[];
    uint2* sBh  = (uint2*)smem;
    uint2* sBl  = (uint2*)(smem + 12288);
    float* cr   = (float*)(smem + 24576);

    const int tid  = threadIdx.x;
    const int lane = tid & 31, wid = tid >> 5;
    const int gr   = lane >> 2, tig = lane & 3;

    for (int i = tid; i < 1536; i += 256) {
        int mat = i >> 8, rem = i & 255;
        int f = rem >> 5, l = rem & 31;
        int nt = f >> 1, kf = f & 1;
        int n = nt * 8 + (l >> 2), k0 = kf * 16 + ((l & 3) << 1);
        const float* Wr = Wt + mat * 1024 + n * 32 + k0;
        uint32_t h0, l0, h1, l1;
        pack_hl(Wr[0], Wr[1], h0, l0);
        pack_hl(Wr[8], Wr[9], h1, l1);
        sBh[i] = make_uint2(h0, h1);
        sBl[i] = make_uint2(l0, l1);
    }
    __syncthreads();

    const int nl0 = tid >> 5;
    const int u   = lane;
    const int matS1 = (wid == 0) ? 0 : (wid < 4) ? 1 : 2;

    for (int s = blockIdx.x; s < nStrips; s += gridDim.x) {
        const int nodeBase = s << 4;
        float Xn[2][9];

        #pragma unroll
        for (int cc = 0; cc < 2; cc++) {
            int r0 = nl0 + cc * 8;
            int n  = nodeBase + r0;
            int nc = min(n, nNodes - 1);
            float nrm = 1.0f;
            #pragma unroll
            for (int t = 0; t < 9; t++) {
                float v = X[((size_t)nc * 9 + t) * 32 + u];
                Xn[cc][t] = v; nrm += v * v;
            }
            float inv = __fdividef(1.0f, nrm);
            #pragma unroll
            for (int t = 0; t < 9; t++) Xn[cc][t] *= inv;

            const float* x = Xn[cc];
            float tr3 = (x[0] + x[4] + x[8]) * (1.0f / 3.0f);
            float* cp = cr + r0 * RS + u;
            cp[0 * 16 * RS] = tr3;
            cp[1 * 16 * RS] = 0.5f * (x[1] - x[3]);
            cp[2 * 16 * RS] = 0.5f * (x[2] - x[6]);
            cp[3 * 16 * RS] = 0.5f * (x[5] - x[7]);
            cp[4 * 16 * RS] = x[0] - tr3;
            cp[5 * 16 * RS] = 0.5f * (x[1] + x[3]);
            cp[6 * 16 * RS] = 0.5f * (x[2] + x[6]);
            cp[7 * 16 * RS] = x[4] - tr3;
            cp[8 * 16 * RS] = 0.5f * (x[5] + x[7]);
        }
        __syncthreads();

        gemm_tile(cr, sBh, sBl, wid, matS1, gr, tig, lane, 0, 4, 16 * wid);
        if (wid < 4)
            gemm_tile(cr, sBh, sBl, 8, 2, gr, tig, lane, wid, wid + 1, RT8_BASE);
        __syncthreads();

        #pragma unroll
        for (int cc = 0; cc < 2; cc++) {
            int r0 = nl0 + cc * 8;
            int n  = nodeBase + r0;
            float* rp = cr + r0 * RS + u;
            float Ip  = rp[0 * 16 * RS];
            float a01 = rp[1 * 16 * RS];
            float a02 = rp[2 * 16 * RS];
            float a12 = rp[3 * 16 * RS];
            float s00 = rp[4 * 16 * RS];
            float s01 = rp[5 * 16 * RS];
            float s02 = rp[6 * 16 * RS];
            float s11 = rp[7 * 16 * RS];
            float s12 = rp[9 * 16 * RS];
            float s22 = -(s00 + s11);

            float sI = 0.f, sA = 0.f, sS = 0.f;
            if (n < nNodes) {
                float* ap = g_acc + (size_t)n * 96 + u * 3;
                sI = ap[0]; sA = ap[1]; sS = ap[2];
                ap[0] = 0.f; ap[1] = 0.f; ap[2] = 0.f;
            }

            float Y[9], G[9];
            Y[0] = Ip + s00;  Y[1] = a01 + s01;  Y[2] = a02 + s02;
            Y[3] = s01 - a01; Y[4] = Ip + s11;   Y[5] = a12 + s12;
            Y[6] = s02 - a02; Y[7] = s12 - a12;  Y[8] = Ip + s22;
            G[0] = Ip*sI + s00*sS;  G[1] = a01*sA + s01*sS;  G[2] = a02*sA + s02*sS;
            G[3] = s01*sS - a01*sA; G[4] = Ip*sI + s11*sS;   G[5] = a12*sA + s12*sS;
            G[6] = s02*sS - a02*sA; G[7] = s12*sS - a12*sA;  G[8] = Ip*sI + s22*sS;

            float M[9];
            #pragma unroll
            for (int i = 0; i < 3; i++)
                #pragma unroll
                for (int l = 0; l < 3; l++) {
                    float a2 = 0.0f;
                    #pragma unroll
                    for (int j = 0; j < 3; j++)
                        a2 += Y[i*3+j] * G[j*3+l] + G[i*3+j] * Y[j*3+l];
                    M[i*3+l] = a2;
                }

            float np = 1.0f;
            #pragma unroll
            for (int t = 0; t < 9; t++) np += M[t] * M[t];
            float inv2 = __fdividef(1.0f, np);
            float trm = (M[0] + M[4] + M[8]) * (1.0f / 3.0f);

            rp[0 * 16 * RS] = trm * inv2;
            rp[1 * 16 * RS] = 0.5f * (M[1] - M[3]) * inv2;
            rp[2 * 16 * RS] = 0.5f * (M[2] - M[6]) * inv2;
            rp[3 * 16 * RS] = 0.5f * (M[5] - M[7]) * inv2;
            rp[4 * 16 * RS] = (M[0] - trm) * inv2;
            rp[5 * 16 * RS] = 0.5f * (M[1] + M[3]) * inv2;
            rp[6 * 16 * RS] = 0.5f * (M[2] + M[6]) * inv2;
            rp[7 * 16 * RS] = (M[4] - trm) * inv2;
            rp[8 * 16 * RS] = 0.5f * (M[5] + M[7]) * inv2;
        }
        __syncthreads();

        gemm_tile(cr, sBh, sBl, wid, matS1 + 3, gr, tig, lane, 0, 4, 16 * wid);
        if (wid < 4)
            gemm_tile(cr, sBh, sBl, 8, 5, gr, tig, lane, wid, wid + 1, RT8_BASE);
        __syncthreads();

        #pragma unroll
        for (int cc = 0; cc < 2; cc++) {
            int r0 = nl0 + cc * 8;
            int n  = nodeBase + r0;
            const float* rp = cr + r0 * RS + u;
            float Ip2 = rp[0 * 16 * RS];
            float b01 = rp[1 * 16 * RS];
            float b02 = rp[2 * 16 * RS];
            float b12 = rp[3 * 16 * RS];
            float t00 = rp[4 * 16 * RS];
            float t01 = rp[5 * 16 * RS];
            float t02 = rp[6 * 16 * RS];
            float t11 = rp[7 * 16 * RS];
            float t12 = rp[9 * 16 * RS];
            float t22 = -(t00 + t11);

            float D[9];
            D[0] = Ip2 + t00;  D[1] = b01 + t01;  D[2] = b02 + t02;
            D[3] = t01 - b01;  D[4] = Ip2 + t11;  D[5] = b12 + t12;
            D[6] = t02 - b02;  D[7] = t12 - b12;  D[8] = Ip2 + t22;

            if (n < nNodes) {
                #pragma unroll
                for (int i = 0; i < 3; i++)
                    #pragma unroll
                    for (int l = 0; l < 3; l++) {
                        float o = Xn[cc][i*3+l] + D[i*3+l];
                        #pragma unroll
                        for (int j = 0; j < 3; j++)
                            o += D[i*3+j] * D[j*3+l];
                        out[((size_t)n * 9 + (i*3+l)) * 32 + u] = o;
                    }
            }
        }
        // no trailing sync: next-strip EW-A writes are same-thread per cell
    }
}

// ---------------------------------------------------------------------------
extern "C" void kernel_launch(void* const* d_in, const int* in_sizes, int n_in,
                              void* d_out, int out_size)
{
    const float* X           = (const float*)d_in[0];
    const int*   edge_index  = (const int*)  d_in[1];
    const float* edge_weight = (const float*)d_in[2];
    const float* edge_attr   = (const float*)d_in[3];
    const float* W1 = (const float*)d_in[4];
    const float* b1 = (const float*)d_in[5];
    const float* W2 = (const float*)d_in[6];
    const float* b2 = (const float*)d_in[7];
    const float* W3 = (const float*)d_in[8];
    const float* b3 = (const float*)d_in[9];
    const float* Wt = (const float*)d_in[10];
    float* out = (float*)d_out;

    int N = in_sizes[0] / 288;   // X is (N,3,3,32)
    if (N > MAXN) N = MAXN;
    int E = in_sizes[2];         // edge_weight is (E,)

    int nStrips = (E + 15) >> 4;
    int grid = (nStrips + 7) / 8;
    if (grid > 296) grid = 296;

    edge_mma_kernel<<<grid, 256>>>(
        edge_attr, edge_index, edge_weight, W1, b1, W2, b2, W3, b3, E);

    int nodeSmem = 24576 + 160 * RS * 4;   // 47616 bytes
    static bool attr_set = false;
    if (!attr_set) {
        cudaFuncSetAttribute(node_mma_kernel,
                             cudaFuncAttributeMaxDynamicSharedMemorySize, nodeSmem);
        attr_set = true;
    }
    int nodeStrips = (N + 15) / 16;
    int nodeGrid = nodeStrips < 592 ? nodeStrips : 592;
    node_mma_kernel<<<nodeGrid, 256, nodeSmem>>>(X, Wt, out, N, nodeStrips);
}

// round 16
// speedup vs baseline: 1.3672x; 1.0114x over previous
#include <cuda_runtime.h>
#include <cuda_bf16.h>
#include <cuda_fp16.h>
#include <cstdint>

// ---------------------------------------------------------------------------
// TensorNet interaction.
//   msg[n] = (component tensors of n) * (per-node scalar sums of edge MLP),
//   so the graph part is a scatter-add of 96 edge-MLP outputs into acc[n][96].
//
// R16: node mixing GEMMs also move to f16 2-term split (was bf16x3):
//   MMA/tile 24 -> 16, B-frag smem 24KB -> 12KB, pack chain shortened.
//   Expected final rel_err ~2e-4 (edge f16x2 contributes 5.7e-5; budget 1e-3).
//   Edge kernel unchanged (R15: f16x2, HMMA-saturated at ~52us).
// ---------------------------------------------------------------------------

#define MAXN 50000
#define PI_F 3.14159265358979323846f
#define CUTOFF_F 5.0f

__device__ float g_acc[(size_t)MAXN * 96];

// fast silu: v*sigmoid(v) = h + h*tanh(h), h = v/2   (1 MUFU)
__device__ __forceinline__ float silu_f(float v) {
    float h = 0.5f * v;
    float t;
    asm("tanh.approx.f32 %0, %1;" : "=f"(t) : "f"(h));
    return h + h * t;
}

// ---- f16 helpers ----
__device__ __forceinline__ uint32_t packf16(float lo, float hi) {
    uint32_t r;
    asm("cvt.rn.f16x2.f32 %0, %1, %2;" : "=r"(r) : "f"(hi), "f"(lo));
    return r;
}
// x = hi(f16) + lo(f16 residual)
__device__ __forceinline__ void pack_hl16(float x, float y, uint32_t& h, uint32_t& l) {
    h = packf16(x, y);
    __half2 hh = *reinterpret_cast<__half2*>(&h);
    float fx = __low2float(hh);
    float fy = __high2float(hh);
    l = packf16(x - fx, y - fy);
}
__device__ __forceinline__ void mma_f16r(float c[4], const uint32_t a[4], uint32_t bx, uint32_t by) {
    asm volatile(
        "mma.sync.aligned.m16n8k16.row.col.f32.f16.f16.f32 "
        "{%0,%1,%2,%3}, {%4,%5,%6,%7}, {%8,%9}, {%0,%1,%2,%3};"
        : "+f"(c[0]), "+f"(c[1]), "+f"(c[2]), "+f"(c[3])
        : "r"(a[0]), "r"(a[1]), "r"(a[2]), "r"(a[3]), "r"(bx), "r"(by));
}
// 2-term split against single-precision-f16 B fragment
__device__ __forceinline__ void mma2(float c[4], const uint32_t ah[4],
                                     const uint32_t al[4], uint2 B) {
    mma_f16r(c, ah, B.x, B.y);
    mma_f16r(c, al, B.x, B.y);
}

// ---------------------------------------------------------------------------
// Edge MLP kernel (R15, unchanged). Warp = 16-edge strip. f16 2-term split.
__global__ void __launch_bounds__(256, 2)
edge_mma_kernel(const float* __restrict__ edge_attr,
                const int*   __restrict__ edge_index,
                const float* __restrict__ edge_weight,
                const float* __restrict__ W1, const float* __restrict__ b1,
                const float* __restrict__ W2, const float* __restrict__ b2,
                const float* __restrict__ W3, const float* __restrict__ b3,
                int E)
{
    __shared__ uint2 sB1[8][32];
    __shared__ uint2 sB2[16][32];
    __shared__ uint2 sB3[48][32];
    __shared__ float sb1[32], sb2[64], sb3[96];

    const int tid = threadIdx.x;

    {
        int i = tid;
        int f = i >> 5, l = i & 31;
        int nt = f >> 1, kf = f & 1;
        int n = nt * 8 + (l >> 2), k0 = kf * 16 + ((l & 3) << 1);
        const float* Wr = W1 + n * 32 + k0;
        sB1[f][l] = make_uint2(packf16(Wr[0], Wr[1]), packf16(Wr[8], Wr[9]));
    }
    for (int i = tid; i < 512; i += 256) {
        int f = i >> 5, l = i & 31;
        int nt = f >> 1, kf = f & 1;
        int n = nt * 8 + (l >> 2), k0 = kf * 16 + ((l & 3) << 1);
        const float* Wr = W2 + n * 32 + k0;
        sB2[f][l] = make_uint2(packf16(Wr[0], Wr[1]), packf16(Wr[8], Wr[9]));
    }
    for (int i = tid; i < 1536; i += 256) {
        int f = i >> 5, l = i & 31;
        int nt = f >> 2, kf = f & 3;
        int n = nt * 8 + (l >> 2), k0 = kf * 16 + ((l & 3) << 1);
        const float* Wr = W3 + n * 64 + k0;
        sB3[f][l] = make_uint2(packf16(Wr[0], Wr[1]), packf16(Wr[8], Wr[9]));
    }
    if (tid < 32) sb1[tid] = b1[tid];
    if (tid < 64) sb2[tid] = b2[tid];
    if (tid < 96) sb3[tid] = b3[tid];
    __syncthreads();

    const int wid = tid >> 5, lane = tid & 31;
    const int r1 = lane >> 2;
    const int tig = lane & 3;
    const int q  = tig << 1;
    const int nStrips = (E + 15) >> 4;

    for (int strip = blockIdx.x * 8 + wid; strip < nStrips;
         strip += gridDim.x * 8) {
        int e0 = strip << 4;
        int eA = e0 + r1, eB = eA + 8;
        int eAc = min(eA, E - 1), eBc = min(eB, E - 1);

        uint32_t A1h[2][4], A1l[2][4];
        #pragma unroll
        for (int kf = 0; kf < 2; kf++) {
            const float* pa = edge_attr + (size_t)eAc * 32 + kf * 16 + q;
            const float* pb = edge_attr + (size_t)eBc * 32 + kf * 16 + q;
            float2 v0 = *(const float2*)pa;
            float2 v1 = *(const float2*)pb;
            float2 v2 = *(const float2*)(pa + 8);
            float2 v3 = *(const float2*)(pb + 8);
            pack_hl16(v0.x, v0.y, A1h[kf][0], A1l[kf][0]);
            pack_hl16(v1.x, v1.y, A1h[kf][1], A1l[kf][1]);
            pack_hl16(v2.x, v2.y, A1h[kf][2], A1l[kf][2]);
            pack_hl16(v3.x, v3.y, A1h[kf][3], A1l[kf][3]);
        }

        float D1[4][4];
        #pragma unroll
        for (int nt = 0; nt < 4; nt++) {
            float bb0 = sb1[nt * 8 + q], bb1 = sb1[nt * 8 + q + 1];
            D1[nt][0] = bb0; D1[nt][1] = bb1; D1[nt][2] = bb0; D1[nt][3] = bb1;
            #pragma unroll
            for (int kf = 0; kf < 2; kf++)
                mma2(D1[nt], A1h[kf], A1l[kf], sB1[nt * 2 + kf][lane]);
        }

        uint32_t A2h[2][4], A2l[2][4];
        #pragma unroll
        for (int kf = 0; kf < 2; kf++) {
            int na = 2 * kf, nb = 2 * kf + 1;
            float sa0 = silu_f(D1[na][0]), sa1 = silu_f(D1[na][1]);
            float sa2 = silu_f(D1[na][2]), sa3 = silu_f(D1[na][3]);
            float sb0 = silu_f(D1[nb][0]), sb1v = silu_f(D1[nb][1]);
            float sb2v = silu_f(D1[nb][2]), sb3v = silu_f(D1[nb][3]);
            pack_hl16(sa0, sa1, A2h[kf][0], A2l[kf][0]);
            pack_hl16(sa2, sa3, A2h[kf][1], A2l[kf][1]);
            pack_hl16(sb0, sb1v, A2h[kf][2], A2l[kf][2]);
            pack_hl16(sb2v, sb3v, A2h[kf][3], A2l[kf][3]);
        }

        float D2[8][4];
        #pragma unroll
        for (int nt = 0; nt < 8; nt++) {
            float bb0 = sb2[nt * 8 + q], bb1 = sb2[nt * 8 + q + 1];
            D2[nt][0] = bb0; D2[nt][1] = bb1; D2[nt][2] = bb0; D2[nt][3] = bb1;
            #pragma unroll
            for (int kf = 0; kf < 2; kf++)
                mma2(D2[nt], A2h[kf], A2l[kf], sB2[nt * 2 + kf][lane]);
        }

        uint32_t A3h[4][4], A3l[4][4];
        #pragma unroll
        for (int kf = 0; kf < 4; kf++) {
            int na = 2 * kf, nb = 2 * kf + 1;
            float sa0 = silu_f(D2[na][0]), sa1 = silu_f(D2[na][1]);
            float sa2 = silu_f(D2[na][2]), sa3 = silu_f(D2[na][3]);
            float sb0 = silu_f(D2[nb][0]), sb1v = silu_f(D2[nb][1]);
            float sb2v = silu_f(D2[nb][2]), sb3v = silu_f(D2[nb][3]);
            pack_hl16(sa0, sa1, A3h[kf][0], A3l[kf][0]);
            pack_hl16(sa2, sa3, A3h[kf][1], A3l[kf][1]);
            pack_hl16(sb0, sb1v, A3h[kf][2], A3l[kf][2]);
            pack_hl16(sb2v, sb3v, A3h[kf][3], A3l[kf][3]);
        }

        float D3[12][4];
        #pragma unroll
        for (int nt = 0; nt < 12; nt++) {
            float bb0 = sb3[nt * 8 + q], bb1 = sb3[nt * 8 + q + 1];
            D3[nt][0] = bb0; D3[nt][1] = bb1; D3[nt][2] = bb0; D3[nt][3] = bb1;
            #pragma unroll
            for (int kf = 0; kf < 4; kf++)
                mma2(D3[nt], A3h[kf], A3l[kf], sB3[nt * 4 + kf][lane]);
        }

        // ---- epilogue: silu*Cc, pair lanes -> red.v4 scatter ----
        float wA = edge_weight[eAc], wB = edge_weight[eBc];
        float CcA = (wA < CUTOFF_F)
                  ? 0.5f * (__cosf(wA * (PI_F / CUTOFF_F)) + 1.0f) : 0.0f;
        float CcB = (wB < CUTOFF_F)
                  ? 0.5f * (__cosf(wB * (PI_F / CUTOFF_F)) + 1.0f) : 0.0f;
        int dA = edge_index[E + eAc], dB = edge_index[E + eBc];
        bool okA = eA < E, okB = eB < E;

        int colbase = (tig >> 1) << 2;
        bool isEven = (tig & 1) == 0;
        float* gP = g_acc + (isEven ? (size_t)dA : (size_t)dB) * 96 + colbase;
        bool ok = isEven ? okA : okB;

        #pragma unroll
        for (int nt = 0; nt < 12; nt++) {
            float t0 = silu_f(D3[nt][0]) * CcA;
            float t1 = silu_f(D3[nt][1]) * CcA;
            float t2 = silu_f(D3[nt][2]) * CcB;
            float t3 = silu_f(D3[nt][3]) * CcB;
            float p0 = __shfl_xor_sync(0xFFFFFFFFu, t0, 1);
            float p1 = __shfl_xor_sync(0xFFFFFFFFu, t1, 1);
            float p2 = __shfl_xor_sync(0xFFFFFFFFu, t2, 1);
            float p3 = __shfl_xor_sync(0xFFFFFFFFu, t3, 1);
            float v0 = isEven ? t0 : p2;
            float v1 = isEven ? t1 : p3;
            float v2 = isEven ? p0 : t2;
            float v3 = isEven ? p1 : t3;
            if (ok) {
                asm volatile("red.global.add.v4.f32 [%0], {%1, %2, %3, %4};"
                             :: "l"(gP + nt * 8),
                                "f"(v0), "f"(v1), "f"(v2), "f"(v3) : "memory");
            }
        }
    }
}

// ---------------------------------------------------------------------------
// Node kernel: f16x2 MMA mixing, in-place cr + RT8 rows, no trailing sync.
#define RS 36
#define RT8_BASE 144

__device__ __forceinline__ void gemm_tile(
    float* cr, const uint2* sB,
    int rt, int mat, int gr, int tig, int lane,
    int nt0, int nt1, int wrBase)
{
    const float* crow0 = cr + (16 * rt + gr) * RS;
    const float* crow1 = crow0 + 8 * RS;
    uint32_t Ah[2][4], Al[2][4];
    #pragma unroll
    for (int kf = 0; kf < 2; kf++) {
        int c0 = kf * 16 + 2 * tig;
        float2 v0 = *(const float2*)(crow0 + c0);
        float2 v1 = *(const float2*)(crow1 + c0);
        float2 v2 = *(const float2*)(crow0 + c0 + 8);
        float2 v3 = *(const float2*)(crow1 + c0 + 8);
        pack_hl16(v0.x, v0.y, Ah[kf][0], Al[kf][0]);
        pack_hl16(v1.x, v1.y, Ah[kf][1], Al[kf][1]);
        pack_hl16(v2.x, v2.y, Ah[kf][2], Al[kf][2]);
        pack_hl16(v3.x, v3.y, Ah[kf][3], Al[kf][3]);
    }
    float* wr0 = cr + (wrBase + gr) * RS + 2 * tig;
    float* wr1 = wr0 + 8 * RS;
    #pragma unroll 4
    for (int nt = nt0; nt < nt1; nt++) {
        float D[4] = {0.f, 0.f, 0.f, 0.f};
        #pragma unroll
        for (int kf = 0; kf < 2; kf++)
            mma2(D, Ah[kf], Al[kf], sB[mat * 256 + (nt * 2 + kf) * 32 + lane]);
        *(float2*)(wr0 + nt * 8) = make_float2(D[0], D[1]);
        *(float2*)(wr1 + nt * 8) = make_float2(D[2], D[3]);
    }
}

__global__ void __launch_bounds__(256)
node_mma_kernel(const float* __restrict__ X,
                const float* __restrict__ Wt,
                float* __restrict__ out,
                int nNodes, int nStrips)
{
    extern __shared__ char smem[];
    uint2* sB  = (uint2*)smem;                       // [mat*256 + f*32 + l], 6*256
    float* cr  = (float*)(smem + 12288);             // [160][RS]

    const int tid  = threadIdx.x;
    const int lane = tid & 31, wid = tid >> 5;
    const int gr   = lane >> 2, tig = lane & 3;

    for (int i = tid; i < 1536; i += 256) {
        int mat = i >> 8, rem = i & 255;
        int f = rem >> 5, l = rem & 31;
        int nt = f >> 1, kf = f & 1;
        int n = nt * 8 + (l >> 2), k0 = kf * 16 + ((l & 3) << 1);
        const float* Wr = Wt + mat * 1024 + n * 32 + k0;
        sB[i] = make_uint2(packf16(Wr[0], Wr[1]), packf16(Wr[8], Wr[9]));
    }
    __syncthreads();

    const int nl0 = tid >> 5;
    const int u   = lane;
    const int matS1 = (wid == 0) ? 0 : (wid < 4) ? 1 : 2;

    for (int s = blockIdx.x; s < nStrips; s += gridDim.x) {
        const int nodeBase = s << 4;
        float Xn[2][9];

        // ---------- EW-A: normalize + decompose -> cr rows 0..143 ----------
        #pragma unroll
        for (int cc = 0; cc < 2; cc++) {
            int r0 = nl0 + cc * 8;
            int n  = nodeBase + r0;
            int nc = min(n, nNodes - 1);
            float nrm = 1.0f;
            #pragma unroll
            for (int t = 0; t < 9; t++) {
                float v = X[((size_t)nc * 9 + t) * 32 + u];
                Xn[cc][t] = v; nrm += v * v;
            }
            float inv = __fdividef(1.0f, nrm);
            #pragma unroll
            for (int t = 0; t < 9; t++) Xn[cc][t] *= inv;

            const float* x = Xn[cc];
            float tr3 = (x[0] + x[4] + x[8]) * (1.0f / 3.0f);
            float* cp = cr + r0 * RS + u;
            cp[0 * 16 * RS] = tr3;
            cp[1 * 16 * RS] = 0.5f * (x[1] - x[3]);
            cp[2 * 16 * RS] = 0.5f * (x[2] - x[6]);
            cp[3 * 16 * RS] = 0.5f * (x[5] - x[7]);
            cp[4 * 16 * RS] = x[0] - tr3;
            cp[5 * 16 * RS] = 0.5f * (x[1] + x[3]);
            cp[6 * 16 * RS] = 0.5f * (x[2] + x[6]);
            cp[7 * 16 * RS] = x[4] - tr3;
            cp[8 * 16 * RS] = 0.5f * (x[5] + x[7]);
        }
        __syncthreads();

        // ---------- GEMM stage 1 (mats 0..2) ----------
        gemm_tile(cr, sB, wid, matS1, gr, tig, lane, 0, 4, 16 * wid);
        if (wid < 4)
            gemm_tile(cr, sB, 8, 2, gr, tig, lane, wid, wid + 1, RT8_BASE);
        __syncthreads();

        // ---------- EW-B: msg combine, M = YG+GY, renorm -> cr ----------
        #pragma unroll
        for (int cc = 0; cc < 2; cc++) {
            int r0 = nl0 + cc * 8;
            int n  = nodeBase + r0;
            float* rp = cr + r0 * RS + u;
            float Ip  = rp[0 * 16 * RS];
            float a01 = rp[1 * 16 * RS];
            float a02 = rp[2 * 16 * RS];
            float a12 = rp[3 * 16 * RS];
            float s00 = rp[4 * 16 * RS];
            float s01 = rp[5 * 16 * RS];
            float s02 = rp[6 * 16 * RS];
            float s11 = rp[7 * 16 * RS];
            float s12 = rp[9 * 16 * RS];            // comp8 result at RT8_BASE
            float s22 = -(s00 + s11);

            float sI = 0.f, sA = 0.f, sS = 0.f;
            if (n < nNodes) {
                float* ap = g_acc + (size_t)n * 96 + u * 3;
                sI = ap[0]; sA = ap[1]; sS = ap[2];
                ap[0] = 0.f; ap[1] = 0.f; ap[2] = 0.f;
            }

            float Y[9], G[9];
            Y[0] = Ip + s00;  Y[1] = a01 + s01;  Y[2] = a02 + s02;
            Y[3] = s01 - a01; Y[4] = Ip + s11;   Y[5] = a12 + s12;
            Y[6] = s02 - a02; Y[7] = s12 - a12;  Y[8] = Ip + s22;
            G[0] = Ip*sI + s00*sS;  G[1] = a01*sA + s01*sS;  G[2] = a02*sA + s02*sS;
            G[3] = s01*sS - a01*sA; G[4] = Ip*sI + s11*sS;   G[5] = a12*sA + s12*sS;
            G[6] = s02*sS - a02*sA; G[7] = s12*sS - a12*sA;  G[8] = Ip*sI + s22*sS;

            float M[9];
            #pragma unroll
            for (int i = 0; i < 3; i++)
                #pragma unroll
                for (int l = 0; l < 3; l++) {
                    float a2 = 0.0f;
                    #pragma unroll
                    for (int j = 0; j < 3; j++)
                        a2 += Y[i*3+j] * G[j*3+l] + G[i*3+j] * Y[j*3+l];
                    M[i*3+l] = a2;
                }

            float np = 1.0f;
            #pragma unroll
            for (int t = 0; t < 9; t++) np += M[t] * M[t];
            float inv2 = __fdividef(1.0f, np);
            float trm = (M[0] + M[4] + M[8]) * (1.0f / 3.0f);

            rp[0 * 16 * RS] = trm * inv2;
            rp[1 * 16 * RS] = 0.5f * (M[1] - M[3]) * inv2;
            rp[2 * 16 * RS] = 0.5f * (M[2] - M[6]) * inv2;
            rp[3 * 16 * RS] = 0.5f * (M[5] - M[7]) * inv2;
            rp[4 * 16 * RS] = (M[0] - trm) * inv2;
            rp[5 * 16 * RS] = 0.5f * (M[1] + M[3]) * inv2;
            rp[6 * 16 * RS] = 0.5f * (M[2] + M[6]) * inv2;
            rp[7 * 16 * RS] = (M[4] - trm) * inv2;
            rp[8 * 16 * RS] = 0.5f * (M[5] + M[7]) * inv2;
        }
        __syncthreads();

        // ---------- GEMM stage 2 (mats 3..5) ----------
        gemm_tile(cr, sB, wid, matS1 + 3, gr, tig, lane, 0, 4, 16 * wid);
        if (wid < 4)
            gemm_tile(cr, sB, 8, 5, gr, tig, lane, wid, wid + 1, RT8_BASE);
        __syncthreads();

        // ---------- EW-C: D, out = Xn + D + D@D ----------
        #pragma unroll
        for (int cc = 0; cc < 2; cc++) {
            int r0 = nl0 + cc * 8;
            int n  = nodeBase + r0;
            const float* rp = cr + r0 * RS + u;
            float Ip2 = rp[0 * 16 * RS];
            float b01 = rp[1 * 16 * RS];
            float b02 = rp[2 * 16 * RS];
            float b12 = rp[3 * 16 * RS];
            float t00 = rp[4 * 16 * RS];
            float t01 = rp[5 * 16 * RS];
            float t02 = rp[6 * 16 * RS];
            float t11 = rp[7 * 16 * RS];
            float t12 = rp[9 * 16 * RS];            // comp8 result at RT8_BASE
            float t22 = -(t00 + t11);

            float D[9];
            D[0] = Ip2 + t00;  D[1] = b01 + t01;  D[2] = b02 + t02;
            D[3] = t01 - b01;  D[4] = Ip2 + t11;  D[5] = b12 + t12;
            D[6] = t02 - b02;  D[7] = t12 - b12;  D[8] = Ip2 + t22;

            if (n < nNodes) {
                #pragma unroll
                for (int i = 0; i < 3; i++)
                    #pragma unroll
                    for (int l = 0; l < 3; l++) {
                        float o = Xn[cc][i*3+l] + D[i*3+l];
                        #pragma unroll
                        for (int j = 0; j < 3; j++)
                            o += D[i*3+j] * D[j*3+l];
                        out[((size_t)n * 9 + (i*3+l)) * 32 + u] = o;
                    }
            }
        }
        // no trailing sync: next-strip EW-A writes are same-thread per cell
    }
}

// ---------------------------------------------------------------------------
extern "C" void kernel_launch(void* const* d_in, const int* in_sizes, int n_in,
                              void* d_out, int out_size)
{
    const float* X           = (const float*)d_in[0];
    const int*   edge_index  = (const int*)  d_in[1];
    const float* edge_weight = (const float*)d_in[2];
    const float* edge_attr   = (const float*)d_in[3];
    const float* W1 = (const float*)d_in[4];
    const float* b1 = (const float*)d_in[5];
    const float* W2 = (const float*)d_in[6];
    const float* b2 = (const float*)d_in[7];
    const float* W3 = (const float*)d_in[8];
    const float* b3 = (const float*)d_in[9];
    const float* Wt = (const float*)d_in[10];
    float* out = (float*)d_out;

    int N = in_sizes[0] / 288;   // X is (N,3,3,32)
    if (N > MAXN) N = MAXN;
    int E = in_sizes[2];         // edge_weight is (E,)

    int nStrips = (E + 15) >> 4;
    int grid = (nStrips + 7) / 8;
    if (grid > 296) grid = 296;

    edge_mma_kernel<<<grid, 256>>>(
        edge_attr, edge_index, edge_weight, W1, b1, W2, b2, W3, b3, E);

    int nodeSmem = 12288 + 160 * RS * 4;   // 35328 bytes
    static bool attr_set = false;
    if (!attr_set) {
        cudaFuncSetAttribute(node_mma_kernel,
                             cudaFuncAttributeMaxDynamicSharedMemorySize, nodeSmem);
        attr_set = true;
    }
    int nodeStrips = (N + 15) / 16;
    int nodeGrid = nodeStrips < 592 ? nodeStrips : 592;
    node_mma_kernel<<<nodeGrid, 256, nodeSmem>>>(X, Wt, out, N, nodeStrips);
}